// round 10
// baseline (speedup 1.0000x reference)
#include <cuda_runtime.h>
#include <cuda_bf16.h>
#include <cstdint>
#include <math.h>

#define B_ 2
#define S_ 2048
#define C_ 2048
#define H_ 32
#define C3 6144
#define BS (B_*S_)

// Scratch (allocation-free device globals)
__device__ float g_qkv[BS * C3];
__device__ __nv_bfloat16 g_xhi[BS * C_],  g_xlo[BS * C_];
__device__ __nv_bfloat16 g_wqhi[C3 * C_], g_wqlo[C3 * C_];
__device__ __nv_bfloat16 g_wohi[C_ * C_], g_wolo[C_ * C_];
__device__ __nv_bfloat16 g_qhi[BS * C_],  g_qlo[BS * C_];
__device__ __nv_bfloat16 g_khi[BS * C_],  g_klo[BS * C_];
__device__ __nv_bfloat16 g_vthi[(size_t)B_ * H_ * 64 * S_], g_vtlo[(size_t)B_ * H_ * 64 * S_];
__device__ __nv_bfloat16 g_atthi[BS * C_], g_attlo[BS * C_];

__device__ __forceinline__ void mma_bf16(float4 &d,
    uint32_t a0, uint32_t a1, uint32_t a2, uint32_t a3, uint32_t b0, uint32_t b1)
{
    asm volatile("mma.sync.aligned.m16n8k16.row.col.f32.bf16.bf16.f32 "
        "{%0,%1,%2,%3}, {%4,%5,%6,%7}, {%8,%9}, {%0,%1,%2,%3};"
        : "+f"(d.x), "+f"(d.y), "+f"(d.z), "+f"(d.w)
        : "r"(a0), "r"(a1), "r"(a2), "r"(a3), "r"(b0), "r"(b1));
}

__device__ __forceinline__ uint4 ldm_x4(uint32_t addr) {
    uint4 r;
    asm volatile("ldmatrix.sync.aligned.m8n8.x4.shared.b16 {%0,%1,%2,%3}, [%4];"
        : "=r"(r.x), "=r"(r.y), "=r"(r.z), "=r"(r.w) : "r"(addr));
    return r;
}

__device__ __forceinline__ void cp16(uint32_t saddr, const void* g) {
    asm volatile("cp.async.cg.shared.global [%0], [%1], 16;" :: "r"(saddr), "l"(g));
}
#define CP_COMMIT() asm volatile("cp.async.commit_group;")

__device__ __forceinline__ uint32_t pack2(__nv_bfloat16 a, __nv_bfloat16 b) {
    __nv_bfloat162 t; t.x = a; t.y = b;
    return *reinterpret_cast<uint32_t*>(&t);
}

__device__ __forceinline__ void split2(float a, float b, uint32_t &hi, uint32_t &lo) {
    __nv_bfloat16 ha = __float2bfloat16_rn(a), hb = __float2bfloat16_rn(b);
    __nv_bfloat16 la = __float2bfloat16_rn(a - __bfloat162float(ha));
    __nv_bfloat16 lb = __float2bfloat16_rn(b - __bfloat162float(hb));
    hi = pack2(ha, hb); lo = pack2(la, lb);
}

// fp32 -> hi/lo bf16 split
__global__ __launch_bounds__(256) void split_kernel(
    const float* __restrict__ in, __nv_bfloat16* __restrict__ hi,
    __nv_bfloat16* __restrict__ lo, int n4)
{
    int i = blockIdx.x * blockDim.x + threadIdx.x;
    if (i >= n4) return;
    float4 v = ((const float4*)in)[i];
    uint32_t h0, l0, h1, l1;
    split2(v.x, v.y, h0, l0);
    split2(v.z, v.w, h1, l1);
    uint32_t* hi32 = (uint32_t*)hi;
    uint32_t* lo32 = (uint32_t*)lo;
    hi32[2*i] = h0; hi32[2*i+1] = h1;
    lo32[2*i] = l0; lo32[2*i+1] = l1;
}

// ---------------------------------------------------------------------------
// bf16x3 GEMM v3: block 128x256, warp tile 64x64 (2m x 4n), BK=32, 4-stage
// cp.async, 1 CTA/SM. Smem row = 64B = 4 chunks; chunk ch at phys ch^((row>>1)&3).
// Stage = [Ahi 8K | Alo 8K | Bhi 16K | Blo 16K] = 48KB; 4 stages = 192KB.
// Two-phase terms per iter: (hh + lh) with B-hi resident, then hl with B-lo,
// caps live regs ~200.
// ---------------------------------------------------------------------------
#define GSTAGES 4
#define GSTAGE_BYTES 49152
#define GEMM_SMEM (GSTAGES * GSTAGE_BYTES)   // 196608

__global__ __launch_bounds__(256) void gemm_bf16x3(
    const __nv_bfloat16* __restrict__ Ahi, const __nv_bfloat16* __restrict__ Alo,
    const __nv_bfloat16* __restrict__ Bhi, const __nv_bfloat16* __restrict__ Blo,
    float* __restrict__ C, int M, int N, int K)
{
    extern __shared__ uint8_t gsm8[];
    const uint32_t sbase = (uint32_t)__cvta_generic_to_shared(gsm8);

    const int tid  = threadIdx.x;
    const int lane = tid & 31, wid = tid >> 5;
    const int g = lane >> 2, c = lane & 3;
    const int wm = wid >> 2, wn = wid & 3;    // 2m x 4n
    const int m0 = blockIdx.y * 128, n0 = blockIdx.x * 256;
    const int rsu = K >> 3;                   // uint4 per gmem row

    // cp.async mapping: thread -> (row, 2 chunks); A 128 rows, B 2x128 rows
    const int crow = tid >> 1;
    const int cc0  = (tid & 1) * 2;
    const int csw  = (crow >> 1) & 3;
    const uint32_t soff0 = crow * 64 + ((cc0 ^ csw) << 4);
    const uint32_t soff1 = crow * 64 + (((cc0 + 1) ^ csw) << 4);
    const uint4* gAh  = (const uint4*)Ahi + (size_t)(m0 + crow) * rsu + cc0;
    const uint4* gAl  = (const uint4*)Alo + (size_t)(m0 + crow) * rsu + cc0;
    const uint4* gBh0 = (const uint4*)Bhi + (size_t)(n0 + crow) * rsu + cc0;
    const uint4* gBl0 = (const uint4*)Blo + (size_t)(n0 + crow) * rsu + cc0;
    const uint4* gBh1 = (const uint4*)Bhi + (size_t)(n0 + 128 + crow) * rsu + cc0;
    const uint4* gBl1 = (const uint4*)Blo + (size_t)(n0 + 128 + crow) * rsu + cc0;

    // fragment (ldmatrix) per-lane offsets within an array
    const int sub  = lane >> 3;
    const int arow = wm * 64 + ((sub & 1) << 3) + (lane & 7);
    const int chA  = sub >> 1;
    const uint32_t aoffA0 = arow * 64 + ((chA ^ ((arow >> 1) & 3)) << 4);
    const uint32_t aoffA1 = aoffA0 ^ 32;                 // k16 tile 1 (chunk+2)
    const int brow = wn * 64 + (lane & 7);
    const uint32_t aoffB = brow * 64 + (((lane >> 3) ^ ((brow >> 1) & 3)) << 4);

    float4 d[4][8];
#pragma unroll
    for (int i = 0; i < 4; i++)
#pragma unroll
        for (int j = 0; j < 8; j++) d[i][j] = make_float4(0.f, 0.f, 0.f, 0.f);

    auto issue = [&](int tile) {
        const uint32_t sb = sbase + (tile & (GSTAGES - 1)) * GSTAGE_BYTES;
        const int kc = tile * 4;
        cp16(sb + soff0,                gAh  + kc);  cp16(sb + soff1,                gAh  + kc + 1);
        cp16(sb + 8192  + soff0,        gAl  + kc);  cp16(sb + 8192  + soff1,        gAl  + kc + 1);
        cp16(sb + 16384 + soff0,        gBh0 + kc);  cp16(sb + 16384 + soff1,        gBh0 + kc + 1);
        cp16(sb + 16384 + 8192 + soff0, gBh1 + kc);  cp16(sb + 16384 + 8192 + soff1, gBh1 + kc + 1);
        cp16(sb + 32768 + soff0,        gBl0 + kc);  cp16(sb + 32768 + soff1,        gBl0 + kc + 1);
        cp16(sb + 32768 + 8192 + soff0, gBl1 + kc);  cp16(sb + 32768 + 8192 + soff1, gBl1 + kc + 1);
    };

    const int nit = K >> 5;
    issue(0); CP_COMMIT();
    issue(1); CP_COMMIT();
    issue(2); CP_COMMIT();

    for (int it = 0; it < nit; it++) {
        const int rem = nit - 1 - it;
        if (rem >= 2)      { asm volatile("cp.async.wait_group 2;"); }
        else if (rem == 1) { asm volatile("cp.async.wait_group 1;"); }
        else               { asm volatile("cp.async.wait_group 0;"); }
        __syncthreads();
        if (it + 3 < nit) { issue(it + 3); CP_COMMIT(); }

        const uint32_t sb   = sbase + (it & (GSTAGES - 1)) * GSTAGE_BYTES;
        const uint32_t bAh  = sb + aoffA0;
        const uint32_t bAh1 = sb + aoffA1;
        const uint32_t bAl  = sb + 8192 + aoffA0;
        const uint32_t bAl1 = sb + 8192 + aoffA1;
        const uint32_t bBh  = sb + 16384 + aoffB;
        const uint32_t bBl  = sb + 32768 + aoffB;

        uint4 bf[8];
        // ---- phase 1: B-hi resident -> hh + lh terms ----
#pragma unroll
        for (int in_ = 0; in_ < 8; in_++) bf[in_] = ldm_x4(bBh + in_ * 512);
#pragma unroll
        for (int im = 0; im < 4; im++) {
            uint4 ah0 = ldm_x4(bAh  + im * 1024);
            uint4 ah1 = ldm_x4(bAh1 + im * 1024);
            uint4 al0 = ldm_x4(bAl  + im * 1024);
            uint4 al1 = ldm_x4(bAl1 + im * 1024);
#pragma unroll
            for (int in_ = 0; in_ < 8; in_++) {
                mma_bf16(d[im][in_], ah0.x, ah0.y, ah0.z, ah0.w, bf[in_].x, bf[in_].y);
                mma_bf16(d[im][in_], al0.x, al0.y, al0.z, al0.w, bf[in_].x, bf[in_].y);
                mma_bf16(d[im][in_], ah1.x, ah1.y, ah1.z, ah1.w, bf[in_].z, bf[in_].w);
                mma_bf16(d[im][in_], al1.x, al1.y, al1.z, al1.w, bf[in_].z, bf[in_].w);
            }
        }
        // ---- phase 2: B-lo resident -> hl terms ----
#pragma unroll
        for (int in_ = 0; in_ < 8; in_++) bf[in_] = ldm_x4(bBl + in_ * 512);
#pragma unroll
        for (int im = 0; im < 4; im++) {
            uint4 ah0 = ldm_x4(bAh  + im * 1024);
            uint4 ah1 = ldm_x4(bAh1 + im * 1024);
#pragma unroll
            for (int in_ = 0; in_ < 8; in_++) {
                mma_bf16(d[im][in_], ah0.x, ah0.y, ah0.z, ah0.w, bf[in_].x, bf[in_].y);
                mma_bf16(d[im][in_], ah1.x, ah1.y, ah1.z, ah1.w, bf[in_].z, bf[in_].w);
            }
        }
    }

#pragma unroll
    for (int im = 0; im < 4; im++)
#pragma unroll
        for (int in_ = 0; in_ < 8; in_++) {
            int row = m0 + wm * 64 + im * 16 + g;
            int col = n0 + wn * 64 + in_ * 8 + 2 * c;
            *(float2*)&C[(size_t)row * N + col]       = make_float2(d[im][in_].x, d[im][in_].y);
            *(float2*)&C[(size_t)(row + 8) * N + col] = make_float2(d[im][in_].z, d[im][in_].w);
        }
}

// ---------------------------------------------------------------------------
// LN (per-head) + rotary; q pre-scaled by 1/8; writes split bf16 q/k.
// ---------------------------------------------------------------------------
__global__ __launch_bounds__(256) void ln_rope_kernel(
    const float* __restrict__ qkv, const float* __restrict__ rope,
    const float* __restrict__ qg, const float* __restrict__ qb,
    const float* __restrict__ kg, const float* __restrict__ kb,
    __nv_bfloat16* __restrict__ qhi, __nv_bfloat16* __restrict__ qlo,
    __nv_bfloat16* __restrict__ khi, __nv_bfloat16* __restrict__ klo)
{
    int wid  = (blockIdx.x * blockDim.x + threadIdx.x) >> 5;
    int lane = threadIdx.x & 31;
    int which = wid & 1;
    int rowh  = wid >> 1;
    int h  = rowh & 31;
    int bs = rowh >> 5;
    int s  = bs & (S_ - 1);

    const float* p = qkv + (size_t)bs * C3 + h * 192 + which * 64;
    float x0 = p[lane];
    float x1 = p[lane + 32];

    float sum = x0 + x1;
#pragma unroll
    for (int off = 16; off > 0; off >>= 1) sum += __shfl_xor_sync(0xffffffffu, sum, off);
    float mean = sum * (1.0f / 64.0f);
    float d0 = x0 - mean, d1 = x1 - mean;
    float vs = d0 * d0 + d1 * d1;
#pragma unroll
    for (int off = 16; off > 0; off >>= 1) vs += __shfl_xor_sync(0xffffffffu, vs, off);
    float rstd = rsqrtf(vs * (1.0f / 64.0f) + 1e-5f);

    const float* gm = which ? kg : qg;
    const float* bt = which ? kb : qb;
    float y0 = d0 * rstd * gm[lane]      + bt[lane];
    float y1 = d1 * rstd * gm[lane + 32] + bt[lane + 32];

    float pr0 = __shfl_xor_sync(0xffffffffu, y0, 1);
    float pr1 = __shfl_xor_sync(0xffffffffu, y1, 1);
    int j = lane & 1;
    const float* rb = rope + s * 128;

    int i0 = lane >> 1;
    float e0 = j ? pr0 : y0;
    float o0 = j ? y0 : pr0;
    float out0 = rb[i0 * 4 + j * 2 + 0] * e0 + rb[i0 * 4 + j * 2 + 1] * o0;

    int i1 = (lane + 32) >> 1;
    float e1 = j ? pr1 : y1;
    float o1 = j ? y1 : pr1;
    float out1 = rb[i1 * 4 + j * 2 + 0] * e1 + rb[i1 * 4 + j * 2 + 1] * o1;

    if (which == 0) { out0 *= 0.125f; out1 *= 0.125f; }

    __nv_bfloat16* hi = which ? khi : qhi;
    __nv_bfloat16* lo = which ? klo : qlo;
    size_t base = (size_t)bs * C_ + h * 64;
    __nv_bfloat16 h0 = __float2bfloat16_rn(out0);
    __nv_bfloat16 h1 = __float2bfloat16_rn(out1);
    hi[base + lane]      = h0;
    hi[base + lane + 32] = h1;
    lo[base + lane]      = __float2bfloat16_rn(out0 - __bfloat162float(h0));
    lo[base + lane + 32] = __float2bfloat16_rn(out1 - __bfloat162float(h1));
}

// ---------------------------------------------------------------------------
// V transpose + split: qkv v-slice [b][s][h][d] -> vt[b][h][d][s] bf16 hi/lo
// ---------------------------------------------------------------------------
__global__ __launch_bounds__(256) void vt_kernel(
    const float* __restrict__ qkv,
    __nv_bfloat16* __restrict__ vthi, __nv_bfloat16* __restrict__ vtlo)
{
    __shared__ __nv_bfloat16 shi[64][72];
    __shared__ __nv_bfloat16 slo[64][72];

    const int tid = threadIdx.x;
    const int s0 = blockIdx.x * 64, h = blockIdx.y, b = blockIdx.z;
    const int tok = tid >> 2, q = tid & 3;

#pragma unroll
    for (int it = 0; it < 4; it++) {
        int dd = q * 16 + it * 4;
        float4 v = *(const float4*)&qkv[(size_t)(b * S_ + s0 + tok) * C3 + h * 192 + 128 + dd];
        float vv[4] = {v.x, v.y, v.z, v.w};
#pragma unroll
        for (int j = 0; j < 4; j++) {
            __nv_bfloat16 hb = __float2bfloat16_rn(vv[j]);
            shi[dd + j][tok] = hb;
            slo[dd + j][tok] = __float2bfloat16_rn(vv[j] - __bfloat162float(hb));
        }
    }
    __syncthreads();

    const int dr = tid >> 2, cq = tid & 3;
    size_t gbase = ((size_t)(b * H_ + h) * 64 + dr) * S_ + s0 + cq * 16;
#pragma unroll
    for (int half = 0; half < 2; half++) {
        *(uint4*)&vthi[gbase + half * 8] = *(const uint4*)&shi[dr][cq * 16 + half * 8];
        *(uint4*)&vtlo[gbase + half * 8] = *(const uint4*)&slo[dr][cq * 16 + half * 8];
    }
}

// ---------------------------------------------------------------------------
// Flash attention, bf16x3, cp.async double-buffered (unchanged from R7).
// ---------------------------------------------------------------------------
#define SW(row, ch) ((row) * 32 + (((ch) ^ ((row) & 7)) << 2))
#define ATT_SMEM (2 * 4 * 8192)

__global__ __launch_bounds__(256) void attn_bf16x3(
    const __nv_bfloat16* __restrict__ qhi, const __nv_bfloat16* __restrict__ qlo,
    const __nv_bfloat16* __restrict__ khi, const __nv_bfloat16* __restrict__ klo,
    const __nv_bfloat16* __restrict__ vthi, const __nv_bfloat16* __restrict__ vtlo,
    __nv_bfloat16* __restrict__ atthi, __nv_bfloat16* __restrict__ attlo)
{
    extern __shared__ uint8_t asm8[];
    uint32_t* dsmw = (uint32_t*)asm8;
    const uint32_t sabase = (uint32_t)__cvta_generic_to_shared(asm8);

    const int tid = threadIdx.x, lane = tid & 31, wid = tid >> 5;
    const int g = lane >> 2, c = lane & 3;
    const int q0 = blockIdx.x * 128;
    const int h = blockIdx.y, b = blockIdx.z;
    const int w16 = wid * 16;

    const uint32_t* qh32 = (const uint32_t*)qhi;
    const uint32_t* ql32 = (const uint32_t*)qlo;
    size_t r0 = (size_t)(b * S_ + q0 + w16 + g) * 1024 + h * 32;
    size_t r1 = r0 + 8 * 1024;
    uint32_t Qh[4][4], Ql[4][4];
#pragma unroll
    for (int s = 0; s < 4; s++) {
        int w0 = 8 * s + c;
        Qh[s][0] = qh32[r0 + w0];     Qh[s][1] = qh32[r1 + w0];
        Qh[s][2] = qh32[r0 + w0 + 4]; Qh[s][3] = qh32[r1 + w0 + 4];
        Ql[s][0] = ql32[r0 + w0];     Ql[s][1] = ql32[r1 + w0];
        Ql[s][2] = ql32[r0 + w0 + 4]; Ql[s][3] = ql32[r1 + w0 + 4];
    }

    const uint4* kh4 = (const uint4*)khi;
    const uint4* kl4 = (const uint4*)klo;
    const uint4* vh4 = (const uint4*)vthi;
    const uint4* vl4 = (const uint4*)vtlo;

    float m_lo = -1e30f, m_hi = -1e30f, l_lo = 0.f, l_hi = 0.f;
    float4 acc[8];
#pragma unroll
    for (int nt = 0; nt < 8; nt++) acc[nt] = make_float4(0.f, 0.f, 0.f, 0.f);

    const int trow = tid & 63;
    const int tch0 = tid >> 6;

    auto issueA = [&](int i) {
        const uint32_t sb = sabase + (i & 1) * 32768;
        const int kv0 = i * 64;
        const size_t kg = (size_t)(b * S_ + kv0 + trow) * 256 + h * 8;
        const size_t vg = ((size_t)(b * H_ + h) * 64 + trow) * 256 + (size_t)(kv0 >> 3);
#pragma unroll
        for (int p = 0; p < 2; p++) {
            const int ch = tch0 + 4 * p;
            const uint32_t so = trow * 128 + ((ch ^ (trow & 7)) << 4);
            cp16(sb + so,         kh4 + kg + ch);
            cp16(sb + 8192  + so, kl4 + kg + ch);
            cp16(sb + 16384 + so, vh4 + vg + ch);
            cp16(sb + 24576 + so, vl4 + vg + ch);
        }
    };

    issueA(0); CP_COMMIT();

    for (int i = 0; i < 32; i++) {
        asm volatile("cp.async.wait_group 0;");
        __syncthreads();
        if (i + 1 < 32) { issueA(i + 1); CP_COMMIT(); }

        const uint32_t* sKh = dsmw + ((i & 1) * 4 + 0) * 2048;
        const uint32_t* sKl = dsmw + ((i & 1) * 4 + 1) * 2048;
        const uint32_t* sVh = dsmw + ((i & 1) * 4 + 2) * 2048;
        const uint32_t* sVl = dsmw + ((i & 1) * 4 + 3) * 2048;

        float4 sf[8];
#pragma unroll
        for (int nt = 0; nt < 8; nt++) sf[nt] = make_float4(0.f, 0.f, 0.f, 0.f);
#pragma unroll
        for (int s = 0; s < 4; s++) {
#pragma unroll
            for (int nt = 0; nt < 8; nt++) {
                int n = nt * 8 + g;
                uint32_t bh0 = sKh[SW(n, 2*s) + c],   bh1 = sKh[SW(n, 2*s+1) + c];
                uint32_t bl0 = sKl[SW(n, 2*s) + c],   bl1 = sKl[SW(n, 2*s+1) + c];
                mma_bf16(sf[nt], Qh[s][0], Qh[s][1], Qh[s][2], Qh[s][3], bh0, bh1);
                mma_bf16(sf[nt], Qh[s][0], Qh[s][1], Qh[s][2], Qh[s][3], bl0, bl1);
                mma_bf16(sf[nt], Ql[s][0], Ql[s][1], Ql[s][2], Ql[s][3], bh0, bh1);
            }
        }

        float tlo = -1e30f, thi = -1e30f;
#pragma unroll
        for (int nt = 0; nt < 8; nt++) {
            tlo = fmaxf(tlo, fmaxf(sf[nt].x, sf[nt].y));
            thi = fmaxf(thi, fmaxf(sf[nt].z, sf[nt].w));
        }
        tlo = fmaxf(tlo, __shfl_xor_sync(0xffffffffu, tlo, 1));
        tlo = fmaxf(tlo, __shfl_xor_sync(0xffffffffu, tlo, 2));
        thi = fmaxf(thi, __shfl_xor_sync(0xffffffffu, thi, 1));
        thi = fmaxf(thi, __shfl_xor_sync(0xffffffffu, thi, 2));

        float mnlo = fmaxf(m_lo, tlo), mnhi = fmaxf(m_hi, thi);
        float corlo = __expf(m_lo - mnlo), corhi = __expf(m_hi - mnhi);
        float slo = 0.f, shi = 0.f;
#pragma unroll
        for (int nt = 0; nt < 8; nt++) {
            sf[nt].x = __expf(sf[nt].x - mnlo);
            sf[nt].y = __expf(sf[nt].y - mnlo);
            sf[nt].z = __expf(sf[nt].z - mnhi);
            sf[nt].w = __expf(sf[nt].w - mnhi);
            slo += sf[nt].x + sf[nt].y;
            shi += sf[nt].z + sf[nt].w;
        }
        slo += __shfl_xor_sync(0xffffffffu, slo, 1);
        slo += __shfl_xor_sync(0xffffffffu, slo, 2);
        shi += __shfl_xor_sync(0xffffffffu, shi, 1);
        shi += __shfl_xor_sync(0xffffffffu, shi, 2);
        l_lo = l_lo * corlo + slo;
        l_hi = l_hi * corhi + shi;
        m_lo = mnlo; m_hi = mnhi;
#pragma unroll
        for (int nt = 0; nt < 8; nt++) {
            acc[nt].x *= corlo; acc[nt].y *= corlo;
            acc[nt].z *= corhi; acc[nt].w *= corhi;
        }

#pragma unroll
        for (int s = 0; s < 4; s++) {
            uint32_t ah0, al0, ah1, al1, ah2, al2, ah3, al3;
            split2(sf[2*s].x,   sf[2*s].y,   ah0, al0);
            split2(sf[2*s].z,   sf[2*s].w,   ah1, al1);
            split2(sf[2*s+1].x, sf[2*s+1].y, ah2, al2);
            split2(sf[2*s+1].z, sf[2*s+1].w, ah3, al3);
#pragma unroll
            for (int nt = 0; nt < 8; nt++) {
                int n = nt * 8 + g;
                uint32_t vh0 = sVh[SW(n, 2*s) + c], vh1 = sVh[SW(n, 2*s+1) + c];
                uint32_t vl0 = sVl[SW(n, 2*s) + c], vl1 = sVl[SW(n, 2*s+1) + c];
                mma_bf16(acc[nt], ah0, ah1, ah2, ah3, vh0, vh1);
                mma_bf16(acc[nt], ah0, ah1, ah2, ah3, vl0, vl1);
                mma_bf16(acc[nt], al0, al1, al2, al3, vh0, vh1);
            }
        }
    }

    float ilo = 1.f / l_lo, ihi = 1.f / l_hi;
    uint32_t* ah32 = (uint32_t*)atthi;
    uint32_t* al32 = (uint32_t*)attlo;
    size_t ob0 = (size_t)(b * S_ + q0 + w16 + g) * 1024 + h * 32;
    size_t ob1 = ob0 + 8 * 1024;
#pragma unroll
    for (int nt = 0; nt < 8; nt++) {
        uint32_t h0, l0, h1, l1;
        split2(acc[nt].x * ilo, acc[nt].y * ilo, h0, l0);
        split2(acc[nt].z * ihi, acc[nt].w * ihi, h1, l1);
        ah32[ob0 + nt * 4 + c] = h0; al32[ob0 + nt * 4 + c] = l0;
        ah32[ob1 + nt * 4 + c] = h1; al32[ob1 + nt * 4 + c] = l1;
    }
}

// ---------------------------------------------------------------------------
extern "C" void kernel_launch(void* const* d_in, const int* in_sizes, int n_in,
                              void* d_out, int out_size)
{
    const float* x     = (const float*)d_in[0];
    const float* rope  = (const float*)d_in[1];
    const float* w_qkv = (const float*)d_in[2];
    const float* w_out = (const float*)d_in[3];
    const float* qg    = (const float*)d_in[4];
    const float* qb    = (const float*)d_in[5];
    const float* kg    = (const float*)d_in[6];
    const float* kb    = (const float*)d_in[7];
    float* out = (float*)d_out;

    cudaFuncSetAttribute(gemm_bf16x3, cudaFuncAttributeMaxDynamicSharedMemorySize, GEMM_SMEM);
    cudaFuncSetAttribute(attn_bf16x3, cudaFuncAttributeMaxDynamicSharedMemorySize, ATT_SMEM);

    float* qkv; cudaGetSymbolAddress((void**)&qkv, g_qkv);
    __nv_bfloat16 *xhi, *xlo, *wqhi, *wqlo, *wohi, *wolo;
    __nv_bfloat16 *qhi, *qlo, *khi, *klo, *vthi, *vtlo, *athi, *atlo;
    cudaGetSymbolAddress((void**)&xhi,  g_xhi);  cudaGetSymbolAddress((void**)&xlo,  g_xlo);
    cudaGetSymbolAddress((void**)&wqhi, g_wqhi); cudaGetSymbolAddress((void**)&wqlo, g_wqlo);
    cudaGetSymbolAddress((void**)&wohi, g_wohi); cudaGetSymbolAddress((void**)&wolo, g_wolo);
    cudaGetSymbolAddress((void**)&qhi,  g_qhi);  cudaGetSymbolAddress((void**)&qlo,  g_qlo);
    cudaGetSymbolAddress((void**)&khi,  g_khi);  cudaGetSymbolAddress((void**)&klo,  g_klo);
    cudaGetSymbolAddress((void**)&vthi, g_vthi); cudaGetSymbolAddress((void**)&vtlo, g_vtlo);
    cudaGetSymbolAddress((void**)&athi, g_atthi);cudaGetSymbolAddress((void**)&atlo, g_attlo);

    // 0) split inputs/weights
    split_kernel<<<(BS * C_ / 4) / 256, 256>>>(x, xhi, xlo, BS * C_ / 4);
    split_kernel<<<(C3 * C_ / 4) / 256, 256>>>(w_qkv, wqhi, wqlo, C3 * C_ / 4);
    split_kernel<<<(C_ * C_ / 4) / 256, 256>>>(w_out, wohi, wolo, C_ * C_ / 4);

    // 1) QKV projection
    gemm_bf16x3<<<dim3(C3 / 256, BS / 128), 256, GEMM_SMEM>>>(
        xhi, xlo, wqhi, wqlo, qkv, BS, C3, C_);

    // 2) LN + rotary -> split q/k
    ln_rope_kernel<<<(BS * H_ * 2) / 8, 256>>>(qkv, rope, qg, qb, kg, kb, qhi, qlo, khi, klo);

    // 3) V transpose + split
    vt_kernel<<<dim3(S_ / 64, H_, B_), 256>>>(qkv, vthi, vtlo);

    // 4) flash attention -> split att
    attn_bf16x3<<<dim3(S_ / 128, H_, B_), 256, ATT_SMEM>>>(
        qhi, qlo, khi, klo, vthi, vtlo, athi, atlo);

    // 5) output projection
    gemm_bf16x3<<<dim3(C_ / 256, BS / 128), 256, GEMM_SMEM>>>(
        athi, atlo, wohi, wolo, out, BS, C_, C_);
}

// round 12
// speedup vs baseline: 1.0848x; 1.0848x over previous
#include <cuda_runtime.h>
#include <cuda_bf16.h>
#include <cstdint>
#include <math.h>

#define B_ 2
#define S_ 2048
#define C_ 2048
#define H_ 32
#define C3 6144
#define BS (B_*S_)

// Scratch (allocation-free device globals)
__device__ float g_qkv[BS * C3];
__device__ __nv_bfloat16 g_xhi[BS * C_],  g_xlo[BS * C_];
__device__ __nv_bfloat16 g_wqhi[C3 * C_], g_wqlo[C3 * C_];
__device__ __nv_bfloat16 g_wohi[C_ * C_], g_wolo[C_ * C_];
__device__ __nv_bfloat16 g_qhi[BS * C_],  g_qlo[BS * C_];
__device__ __nv_bfloat16 g_khi[BS * C_],  g_klo[BS * C_];
__device__ __nv_bfloat16 g_vthi[(size_t)B_ * H_ * 64 * S_], g_vtlo[(size_t)B_ * H_ * 64 * S_];
__device__ __nv_bfloat16 g_atthi[BS * C_], g_attlo[BS * C_];

__device__ __forceinline__ void mma_bf16(float4 &d,
    uint32_t a0, uint32_t a1, uint32_t a2, uint32_t a3, uint32_t b0, uint32_t b1)
{
    asm volatile("mma.sync.aligned.m16n8k16.row.col.f32.bf16.bf16.f32 "
        "{%0,%1,%2,%3}, {%4,%5,%6,%7}, {%8,%9}, {%0,%1,%2,%3};"
        : "+f"(d.x), "+f"(d.y), "+f"(d.z), "+f"(d.w)
        : "r"(a0), "r"(a1), "r"(a2), "r"(a3), "r"(b0), "r"(b1));
}

__device__ __forceinline__ uint4 ldm_x4(uint32_t addr) {
    uint4 r;
    asm volatile("ldmatrix.sync.aligned.m8n8.x4.shared.b16 {%0,%1,%2,%3}, [%4];"
        : "=r"(r.x), "=r"(r.y), "=r"(r.z), "=r"(r.w) : "r"(addr));
    return r;
}

__device__ __forceinline__ void cp16(uint32_t saddr, const void* g) {
    asm volatile("cp.async.cg.shared.global [%0], [%1], 16;" :: "r"(saddr), "l"(g));
}
#define CP_COMMIT() asm volatile("cp.async.commit_group;")

__device__ __forceinline__ uint32_t pack2(__nv_bfloat16 a, __nv_bfloat16 b) {
    __nv_bfloat162 t; t.x = a; t.y = b;
    return *reinterpret_cast<uint32_t*>(&t);
}

__device__ __forceinline__ void split2(float a, float b, uint32_t &hi, uint32_t &lo) {
    __nv_bfloat16 ha = __float2bfloat16_rn(a), hb = __float2bfloat16_rn(b);
    __nv_bfloat16 la = __float2bfloat16_rn(a - __bfloat162float(ha));
    __nv_bfloat16 lb = __float2bfloat16_rn(b - __bfloat162float(hb));
    hi = pack2(ha, hb); lo = pack2(la, lb);
}

// fp32 -> hi/lo bf16 split
__global__ __launch_bounds__(256) void split_kernel(
    const float* __restrict__ in, __nv_bfloat16* __restrict__ hi,
    __nv_bfloat16* __restrict__ lo, int n4)
{
    int i = blockIdx.x * blockDim.x + threadIdx.x;
    if (i >= n4) return;
    float4 v = ((const float4*)in)[i];
    uint32_t h0, l0, h1, l1;
    split2(v.x, v.y, h0, l0);
    split2(v.z, v.w, h1, l1);
    uint32_t* hi32 = (uint32_t*)hi;
    uint32_t* lo32 = (uint32_t*)lo;
    hi32[2*i] = h0; hi32[2*i+1] = h1;
    lo32[2*i] = l0; lo32[2*i+1] = l1;
}

// ---------------------------------------------------------------------------
// bf16x3 GEMM v2 (R7 config): cp.async 3-stage + ldmatrix.
// Block 128x128, BK=32, 256 thr = 8 warps (2m x 4n), warp tile 64x32, 2 CTAs/SM.
// Smem row = 64B = 4 chunks of 16B; chunk ch stored at phys = ch ^ ((row>>1)&3).
// Stage = [Ahi|Alo|Bhi|Blo] x 8KB = 32KB; 3 stages = 96KB dynamic.
// ONE barrier per iter: top barrier (after wait_group) orders prev-iter reads
// before this iter's cp.async writes into stage (it+2)%3 == (it-1)%3.
// ---------------------------------------------------------------------------
#define GSTAGES 3
#define GSTAGE_BYTES (4 * 8192)
#define GEMM_SMEM (GSTAGES * GSTAGE_BYTES)

__global__ __launch_bounds__(256, 2) void gemm_bf16x3(
    const __nv_bfloat16* __restrict__ Ahi, const __nv_bfloat16* __restrict__ Alo,
    const __nv_bfloat16* __restrict__ Bhi, const __nv_bfloat16* __restrict__ Blo,
    float* __restrict__ C, int M, int N, int K)
{
    extern __shared__ uint8_t gsm8[];
    const uint32_t sbase = (uint32_t)__cvta_generic_to_shared(gsm8);

    const int tid  = threadIdx.x;
    const int lane = tid & 31, wid = tid >> 5;
    const int g = lane >> 2, c = lane & 3;
    const int wm = wid >> 2, wn = wid & 3;
    const int m0 = blockIdx.y * 128, n0 = blockIdx.x * 128;
    const int rsu = K >> 3;            // uint4 per gmem row

    // cp.async mapping: thread -> (row, 2 chunks)
    const int crow = tid >> 1;
    const int cc0  = (tid & 1) * 2;
    const int csw  = (crow >> 1) & 3;
    const uint32_t soff0 = crow * 64 + ((cc0 ^ csw) << 4);
    const uint32_t soff1 = crow * 64 + (((cc0 + 1) ^ csw) << 4);
    const uint4* gAh = (const uint4*)Ahi + (size_t)(m0 + crow) * rsu + cc0;
    const uint4* gAl = (const uint4*)Alo + (size_t)(m0 + crow) * rsu + cc0;
    const uint4* gBh = (const uint4*)Bhi + (size_t)(n0 + crow) * rsu + cc0;
    const uint4* gBl = (const uint4*)Blo + (size_t)(n0 + crow) * rsu + cc0;

    // fragment (ldmatrix) per-lane offsets within an array
    const int sub  = lane >> 3;
    const int arow = wm * 64 + ((sub & 1) << 3) + (lane & 7);
    const int chA  = sub >> 1;
    const uint32_t aoffA0 = arow * 64 + ((chA ^ ((arow >> 1) & 3)) << 4);
    const uint32_t aoffA1 = aoffA0 ^ 32;                     // k16 tile 1 (ch+2)
    const int brow = wn * 32 + (lane & 7);
    const uint32_t aoffB = brow * 64 + (((lane >> 3) ^ ((brow >> 1) & 3)) << 4);

    float4 d[4][4];
#pragma unroll
    for (int i = 0; i < 4; i++)
#pragma unroll
        for (int j = 0; j < 4; j++) d[i][j] = make_float4(0.f, 0.f, 0.f, 0.f);

    auto issue = [&](int tile) {
        const uint32_t sb = sbase + (tile % GSTAGES) * GSTAGE_BYTES;
        const int kc = tile * 4;
        cp16(sb + soff0,         gAh + kc);     cp16(sb + soff1,         gAh + kc + 1);
        cp16(sb + 8192  + soff0, gAl + kc);     cp16(sb + 8192  + soff1, gAl + kc + 1);
        cp16(sb + 16384 + soff0, gBh + kc);     cp16(sb + 16384 + soff1, gBh + kc + 1);
        cp16(sb + 24576 + soff0, gBl + kc);     cp16(sb + 24576 + soff1, gBl + kc + 1);
    };

    const int nit = K >> 5;
    issue(0); CP_COMMIT();
    issue(1); CP_COMMIT();

    for (int it = 0; it < nit; it++) {
        if (it + 1 < nit) { asm volatile("cp.async.wait_group 1;"); }
        else              { asm volatile("cp.async.wait_group 0;"); }
        __syncthreads();   // single barrier/iter: orders prev reads vs new writes too
        if (it + 2 < nit) { issue(it + 2); CP_COMMIT(); }

        const uint32_t sb  = sbase + (it % GSTAGES) * GSTAGE_BYTES;
        const uint32_t bA  = sb + aoffA0;
        const uint32_t bA1 = sb + aoffA1;
        const uint32_t bB  = sb + 16384 + aoffB;

        uint4 bh[4], bl[4];
#pragma unroll
        for (int in_ = 0; in_ < 4; in_++) {
            bh[in_] = ldm_x4(bB + in_ * 512);
            bl[in_] = ldm_x4(bB + 8192 + in_ * 512);
        }
#pragma unroll
        for (int im = 0; im < 4; im++) {
            uint4 ah0 = ldm_x4(bA  + im * 1024);          // k16 tile 0: a0..a3
            uint4 ah1 = ldm_x4(bA1 + im * 1024);          // k16 tile 1
            uint4 al0 = ldm_x4(bA  + 8192 + im * 1024);
            uint4 al1 = ldm_x4(bA1 + 8192 + im * 1024);
#pragma unroll
            for (int in_ = 0; in_ < 4; in_++) {
                mma_bf16(d[im][in_], ah0.x, ah0.y, ah0.z, ah0.w, bh[in_].x, bh[in_].y);
                mma_bf16(d[im][in_], ah0.x, ah0.y, ah0.z, ah0.w, bl[in_].x, bl[in_].y);
                mma_bf16(d[im][in_], al0.x, al0.y, al0.z, al0.w, bh[in_].x, bh[in_].y);
                mma_bf16(d[im][in_], ah1.x, ah1.y, ah1.z, ah1.w, bh[in_].z, bh[in_].w);
                mma_bf16(d[im][in_], ah1.x, ah1.y, ah1.z, ah1.w, bl[in_].z, bl[in_].w);
                mma_bf16(d[im][in_], al1.x, al1.y, al1.z, al1.w, bh[in_].z, bh[in_].w);
            }
        }
    }

#pragma unroll
    for (int im = 0; im < 4; im++)
#pragma unroll
        for (int in_ = 0; in_ < 4; in_++) {
            int row = m0 + wm * 64 + im * 16 + g;
            int col = n0 + wn * 32 + in_ * 8 + 2 * c;
            *(float2*)&C[(size_t)row * N + col]       = make_float2(d[im][in_].x, d[im][in_].y);
            *(float2*)&C[(size_t)(row + 8) * N + col] = make_float2(d[im][in_].z, d[im][in_].w);
        }
}

// ---------------------------------------------------------------------------
// LN (per-head) + rotary; q pre-scaled by 1/8; writes split bf16 q/k.
// ---------------------------------------------------------------------------
__global__ __launch_bounds__(256) void ln_rope_kernel(
    const float* __restrict__ qkv, const float* __restrict__ rope,
    const float* __restrict__ qg, const float* __restrict__ qb,
    const float* __restrict__ kg, const float* __restrict__ kb,
    __nv_bfloat16* __restrict__ qhi, __nv_bfloat16* __restrict__ qlo,
    __nv_bfloat16* __restrict__ khi, __nv_bfloat16* __restrict__ klo)
{
    int wid  = (blockIdx.x * blockDim.x + threadIdx.x) >> 5;
    int lane = threadIdx.x & 31;
    int which = wid & 1;
    int rowh  = wid >> 1;
    int h  = rowh & 31;
    int bs = rowh >> 5;
    int s  = bs & (S_ - 1);

    const float* p = qkv + (size_t)bs * C3 + h * 192 + which * 64;
    float x0 = p[lane];
    float x1 = p[lane + 32];

    float sum = x0 + x1;
#pragma unroll
    for (int off = 16; off > 0; off >>= 1) sum += __shfl_xor_sync(0xffffffffu, sum, off);
    float mean = sum * (1.0f / 64.0f);
    float d0 = x0 - mean, d1 = x1 - mean;
    float vs = d0 * d0 + d1 * d1;
#pragma unroll
    for (int off = 16; off > 0; off >>= 1) vs += __shfl_xor_sync(0xffffffffu, vs, off);
    float rstd = rsqrtf(vs * (1.0f / 64.0f) + 1e-5f);

    const float* gm = which ? kg : qg;
    const float* bt = which ? kb : qb;
    float y0 = d0 * rstd * gm[lane]      + bt[lane];
    float y1 = d1 * rstd * gm[lane + 32] + bt[lane + 32];

    float pr0 = __shfl_xor_sync(0xffffffffu, y0, 1);
    float pr1 = __shfl_xor_sync(0xffffffffu, y1, 1);
    int j = lane & 1;
    const float* rb = rope + s * 128;

    int i0 = lane >> 1;
    float e0 = j ? pr0 : y0;
    float o0 = j ? y0 : pr0;
    float out0 = rb[i0 * 4 + j * 2 + 0] * e0 + rb[i0 * 4 + j * 2 + 1] * o0;

    int i1 = (lane + 32) >> 1;
    float e1 = j ? pr1 : y1;
    float o1 = j ? y1 : pr1;
    float out1 = rb[i1 * 4 + j * 2 + 0] * e1 + rb[i1 * 4 + j * 2 + 1] * o1;

    if (which == 0) { out0 *= 0.125f; out1 *= 0.125f; }

    __nv_bfloat16* hi = which ? khi : qhi;
    __nv_bfloat16* lo = which ? klo : qlo;
    size_t base = (size_t)bs * C_ + h * 64;
    __nv_bfloat16 h0 = __float2bfloat16_rn(out0);
    __nv_bfloat16 h1 = __float2bfloat16_rn(out1);
    hi[base + lane]      = h0;
    hi[base + lane + 32] = h1;
    lo[base + lane]      = __float2bfloat16_rn(out0 - __bfloat162float(h0));
    lo[base + lane + 32] = __float2bfloat16_rn(out1 - __bfloat162float(h1));
}

// ---------------------------------------------------------------------------
// V transpose + split: qkv v-slice [b][s][h][d] -> vt[b][h][d][s] bf16 hi/lo
// ---------------------------------------------------------------------------
__global__ __launch_bounds__(256) void vt_kernel(
    const float* __restrict__ qkv,
    __nv_bfloat16* __restrict__ vthi, __nv_bfloat16* __restrict__ vtlo)
{
    __shared__ __nv_bfloat16 shi[64][72];
    __shared__ __nv_bfloat16 slo[64][72];

    const int tid = threadIdx.x;
    const int s0 = blockIdx.x * 64, h = blockIdx.y, b = blockIdx.z;
    const int tok = tid >> 2, q = tid & 3;

#pragma unroll
    for (int it = 0; it < 4; it++) {
        int dd = q * 16 + it * 4;
        float4 v = *(const float4*)&qkv[(size_t)(b * S_ + s0 + tok) * C3 + h * 192 + 128 + dd];
        float vv[4] = {v.x, v.y, v.z, v.w};
#pragma unroll
        for (int j = 0; j < 4; j++) {
            __nv_bfloat16 hb = __float2bfloat16_rn(vv[j]);
            shi[dd + j][tok] = hb;
            slo[dd + j][tok] = __float2bfloat16_rn(vv[j] - __bfloat162float(hb));
        }
    }
    __syncthreads();

    const int dr = tid >> 2, cq = tid & 3;
    size_t gbase = ((size_t)(b * H_ + h) * 64 + dr) * S_ + s0 + cq * 16;
#pragma unroll
    for (int half = 0; half < 2; half++) {
        *(uint4*)&vthi[gbase + half * 8] = *(const uint4*)&shi[dr][cq * 16 + half * 8];
        *(uint4*)&vtlo[gbase + half * 8] = *(const uint4*)&slo[dr][cq * 16 + half * 8];
    }
}

// ---------------------------------------------------------------------------
// Flash attention, bf16x3, cp.async double-buffered (unchanged from R7).
// ---------------------------------------------------------------------------
#define SW(row, ch) ((row) * 32 + (((ch) ^ ((row) & 7)) << 2))
#define ATT_SMEM (2 * 4 * 8192)

__global__ __launch_bounds__(256) void attn_bf16x3(
    const __nv_bfloat16* __restrict__ qhi, const __nv_bfloat16* __restrict__ qlo,
    const __nv_bfloat16* __restrict__ khi, const __nv_bfloat16* __restrict__ klo,
    const __nv_bfloat16* __restrict__ vthi, const __nv_bfloat16* __restrict__ vtlo,
    __nv_bfloat16* __restrict__ atthi, __nv_bfloat16* __restrict__ attlo)
{
    extern __shared__ uint8_t asm8[];
    uint32_t* dsmw = (uint32_t*)asm8;
    const uint32_t sabase = (uint32_t)__cvta_generic_to_shared(asm8);

    const int tid = threadIdx.x, lane = tid & 31, wid = tid >> 5;
    const int g = lane >> 2, c = lane & 3;
    const int q0 = blockIdx.x * 128;
    const int h = blockIdx.y, b = blockIdx.z;
    const int w16 = wid * 16;

    const uint32_t* qh32 = (const uint32_t*)qhi;
    const uint32_t* ql32 = (const uint32_t*)qlo;
    size_t r0 = (size_t)(b * S_ + q0 + w16 + g) * 1024 + h * 32;
    size_t r1 = r0 + 8 * 1024;
    uint32_t Qh[4][4], Ql[4][4];
#pragma unroll
    for (int s = 0; s < 4; s++) {
        int w0 = 8 * s + c;
        Qh[s][0] = qh32[r0 + w0];     Qh[s][1] = qh32[r1 + w0];
        Qh[s][2] = qh32[r0 + w0 + 4]; Qh[s][3] = qh32[r1 + w0 + 4];
        Ql[s][0] = ql32[r0 + w0];     Ql[s][1] = ql32[r1 + w0];
        Ql[s][2] = ql32[r0 + w0 + 4]; Ql[s][3] = ql32[r1 + w0 + 4];
    }

    const uint4* kh4 = (const uint4*)khi;
    const uint4* kl4 = (const uint4*)klo;
    const uint4* vh4 = (const uint4*)vthi;
    const uint4* vl4 = (const uint4*)vtlo;

    float m_lo = -1e30f, m_hi = -1e30f, l_lo = 0.f, l_hi = 0.f;
    float4 acc[8];
#pragma unroll
    for (int nt = 0; nt < 8; nt++) acc[nt] = make_float4(0.f, 0.f, 0.f, 0.f);

    const int trow = tid & 63;
    const int tch0 = tid >> 6;

    auto issueA = [&](int i) {
        const uint32_t sb = sabase + (i & 1) * 32768;
        const int kv0 = i * 64;
        const size_t kg = (size_t)(b * S_ + kv0 + trow) * 256 + h * 8;
        const size_t vg = ((size_t)(b * H_ + h) * 64 + trow) * 256 + (size_t)(kv0 >> 3);
#pragma unroll
        for (int p = 0; p < 2; p++) {
            const int ch = tch0 + 4 * p;
            const uint32_t so = trow * 128 + ((ch ^ (trow & 7)) << 4);
            cp16(sb + so,         kh4 + kg + ch);
            cp16(sb + 8192  + so, kl4 + kg + ch);
            cp16(sb + 16384 + so, vh4 + vg + ch);
            cp16(sb + 24576 + so, vl4 + vg + ch);
        }
    };

    issueA(0); CP_COMMIT();

    for (int i = 0; i < 32; i++) {
        asm volatile("cp.async.wait_group 0;");
        __syncthreads();
        if (i + 1 < 32) { issueA(i + 1); CP_COMMIT(); }

        const uint32_t* sKh = dsmw + ((i & 1) * 4 + 0) * 2048;
        const uint32_t* sKl = dsmw + ((i & 1) * 4 + 1) * 2048;
        const uint32_t* sVh = dsmw + ((i & 1) * 4 + 2) * 2048;
        const uint32_t* sVl = dsmw + ((i & 1) * 4 + 3) * 2048;

        float4 sf[8];
#pragma unroll
        for (int nt = 0; nt < 8; nt++) sf[nt] = make_float4(0.f, 0.f, 0.f, 0.f);
#pragma unroll
        for (int s = 0; s < 4; s++) {
#pragma unroll
            for (int nt = 0; nt < 8; nt++) {
                int n = nt * 8 + g;
                uint32_t bh0 = sKh[SW(n, 2*s) + c],   bh1 = sKh[SW(n, 2*s+1) + c];
                uint32_t bl0 = sKl[SW(n, 2*s) + c],   bl1 = sKl[SW(n, 2*s+1) + c];
                mma_bf16(sf[nt], Qh[s][0], Qh[s][1], Qh[s][2], Qh[s][3], bh0, bh1);
                mma_bf16(sf[nt], Qh[s][0], Qh[s][1], Qh[s][2], Qh[s][3], bl0, bl1);
                mma_bf16(sf[nt], Ql[s][0], Ql[s][1], Ql[s][2], Ql[s][3], bh0, bh1);
            }
        }

        float tlo = -1e30f, thi = -1e30f;
#pragma unroll
        for (int nt = 0; nt < 8; nt++) {
            tlo = fmaxf(tlo, fmaxf(sf[nt].x, sf[nt].y));
            thi = fmaxf(thi, fmaxf(sf[nt].z, sf[nt].w));
        }
        tlo = fmaxf(tlo, __shfl_xor_sync(0xffffffffu, tlo, 1));
        tlo = fmaxf(tlo, __shfl_xor_sync(0xffffffffu, tlo, 2));
        thi = fmaxf(thi, __shfl_xor_sync(0xffffffffu, thi, 1));
        thi = fmaxf(thi, __shfl_xor_sync(0xffffffffu, thi, 2));

        float mnlo = fmaxf(m_lo, tlo), mnhi = fmaxf(m_hi, thi);
        float corlo = __expf(m_lo - mnlo), corhi = __expf(m_hi - mnhi);
        float slo = 0.f, shi = 0.f;
#pragma unroll
        for (int nt = 0; nt < 8; nt++) {
            sf[nt].x = __expf(sf[nt].x - mnlo);
            sf[nt].y = __expf(sf[nt].y - mnlo);
            sf[nt].z = __expf(sf[nt].z - mnhi);
            sf[nt].w = __expf(sf[nt].w - mnhi);
            slo += sf[nt].x + sf[nt].y;
            shi += sf[nt].z + sf[nt].w;
        }
        slo += __shfl_xor_sync(0xffffffffu, slo, 1);
        slo += __shfl_xor_sync(0xffffffffu, slo, 2);
        shi += __shfl_xor_sync(0xffffffffu, shi, 1);
        shi += __shfl_xor_sync(0xffffffffu, shi, 2);
        l_lo = l_lo * corlo + slo;
        l_hi = l_hi * corhi + shi;
        m_lo = mnlo; m_hi = mnhi;
#pragma unroll
        for (int nt = 0; nt < 8; nt++) {
            acc[nt].x *= corlo; acc[nt].y *= corlo;
            acc[nt].z *= corhi; acc[nt].w *= corhi;
        }

#pragma unroll
        for (int s = 0; s < 4; s++) {
            uint32_t ah0, al0, ah1, al1, ah2, al2, ah3, al3;
            split2(sf[2*s].x,   sf[2*s].y,   ah0, al0);
            split2(sf[2*s].z,   sf[2*s].w,   ah1, al1);
            split2(sf[2*s+1].x, sf[2*s+1].y, ah2, al2);
            split2(sf[2*s+1].z, sf[2*s+1].w, ah3, al3);
#pragma unroll
            for (int nt = 0; nt < 8; nt++) {
                int n = nt * 8 + g;
                uint32_t vh0 = sVh[SW(n, 2*s) + c], vh1 = sVh[SW(n, 2*s+1) + c];
                uint32_t vl0 = sVl[SW(n, 2*s) + c], vl1 = sVl[SW(n, 2*s+1) + c];
                mma_bf16(acc[nt], ah0, ah1, ah2, ah3, vh0, vh1);
                mma_bf16(acc[nt], ah0, ah1, ah2, ah3, vl0, vl1);
                mma_bf16(acc[nt], al0, al1, al2, al3, vh0, vh1);
            }
        }
    }

    float ilo = 1.f / l_lo, ihi = 1.f / l_hi;
    uint32_t* ah32 = (uint32_t*)atthi;
    uint32_t* al32 = (uint32_t*)attlo;
    size_t ob0 = (size_t)(b * S_ + q0 + w16 + g) * 1024 + h * 32;
    size_t ob1 = ob0 + 8 * 1024;
#pragma unroll
    for (int nt = 0; nt < 8; nt++) {
        uint32_t h0, l0, h1, l1;
        split2(acc[nt].x * ilo, acc[nt].y * ilo, h0, l0);
        split2(acc[nt].z * ihi, acc[nt].w * ihi, h1, l1);
        ah32[ob0 + nt * 4 + c] = h0; al32[ob0 + nt * 4 + c] = l0;
        ah32[ob1 + nt * 4 + c] = h1; al32[ob1 + nt * 4 + c] = l1;
    }
}

// ---------------------------------------------------------------------------
extern "C" void kernel_launch(void* const* d_in, const int* in_sizes, int n_in,
                              void* d_out, int out_size)
{
    const float* x     = (const float*)d_in[0];
    const float* rope  = (const float*)d_in[1];
    const float* w_qkv = (const float*)d_in[2];
    const float* w_out = (const float*)d_in[3];
    const float* qg    = (const float*)d_in[4];
    const float* qb    = (const float*)d_in[5];
    const float* kg    = (const float*)d_in[6];
    const float* kb    = (const float*)d_in[7];
    float* out = (float*)d_out;

    cudaFuncSetAttribute(gemm_bf16x3, cudaFuncAttributeMaxDynamicSharedMemorySize, GEMM_SMEM);
    cudaFuncSetAttribute(attn_bf16x3, cudaFuncAttributeMaxDynamicSharedMemorySize, ATT_SMEM);

    float* qkv; cudaGetSymbolAddress((void**)&qkv, g_qkv);
    __nv_bfloat16 *xhi, *xlo, *wqhi, *wqlo, *wohi, *wolo;
    __nv_bfloat16 *qhi, *qlo, *khi, *klo, *vthi, *vtlo, *athi, *atlo;
    cudaGetSymbolAddress((void**)&xhi,  g_xhi);  cudaGetSymbolAddress((void**)&xlo,  g_xlo);
    cudaGetSymbolAddress((void**)&wqhi, g_wqhi); cudaGetSymbolAddress((void**)&wqlo, g_wqlo);
    cudaGetSymbolAddress((void**)&wohi, g_wohi); cudaGetSymbolAddress((void**)&wolo, g_wolo);
    cudaGetSymbolAddress((void**)&qhi,  g_qhi);  cudaGetSymbolAddress((void**)&qlo,  g_qlo);
    cudaGetSymbolAddress((void**)&khi,  g_khi);  cudaGetSymbolAddress((void**)&klo,  g_klo);
    cudaGetSymbolAddress((void**)&vthi, g_vthi); cudaGetSymbolAddress((void**)&vtlo, g_vtlo);
    cudaGetSymbolAddress((void**)&athi, g_atthi);cudaGetSymbolAddress((void**)&atlo, g_attlo);

    // 0) split inputs/weights
    split_kernel<<<(BS * C_ / 4) / 256, 256>>>(x, xhi, xlo, BS * C_ / 4);
    split_kernel<<<(C3 * C_ / 4) / 256, 256>>>(w_qkv, wqhi, wqlo, C3 * C_ / 4);
    split_kernel<<<(C_ * C_ / 4) / 256, 256>>>(w_out, wohi, wolo, C_ * C_ / 4);

    // 1) QKV projection
    gemm_bf16x3<<<dim3(C3 / 128, BS / 128), 256, GEMM_SMEM>>>(
        xhi, xlo, wqhi, wqlo, qkv, BS, C3, C_);

    // 2) LN + rotary -> split q/k
    ln_rope_kernel<<<(BS * H_ * 2) / 8, 256>>>(qkv, rope, qg, qb, kg, kb, qhi, qlo, khi, klo);

    // 3) V transpose + split
    vt_kernel<<<dim3(S_ / 64, H_, B_), 256>>>(qkv, vthi, vtlo);

    // 4) flash attention -> split att
    attn_bf16x3<<<dim3(S_ / 128, H_, B_), 256, ATT_SMEM>>>(
        qhi, qlo, khi, klo, vthi, vtlo, athi, atlo);

    // 5) output projection
    gemm_bf16x3<<<dim3(C_ / 128, BS / 128), 256, GEMM_SMEM>>>(
        athi, atlo, wohi, wolo, out, BS, C_, C_);
}

// round 13
// speedup vs baseline: 1.1855x; 1.0929x over previous
#include <cuda_runtime.h>
#include <cuda_bf16.h>
#include <cstdint>
#include <math.h>

#define B_ 2
#define S_ 2048
#define C_ 2048
#define H_ 32
#define C3 6144
#define BS (B_*S_)

// Scratch (allocation-free device globals)
__device__ float g_qkv[BS * C3];
__device__ __nv_bfloat16 g_xhi[BS * C_],  g_xlo[BS * C_];
__device__ __nv_bfloat16 g_wqhi[C3 * C_], g_wqlo[C3 * C_];
__device__ __nv_bfloat16 g_wohi[C_ * C_], g_wolo[C_ * C_];
__device__ __nv_bfloat16 g_atthi[BS * C_], g_attlo[BS * C_];

__device__ __forceinline__ void mma_bf16(float4 &d,
    uint32_t a0, uint32_t a1, uint32_t a2, uint32_t a3, uint32_t b0, uint32_t b1)
{
    asm volatile("mma.sync.aligned.m16n8k16.row.col.f32.bf16.bf16.f32 "
        "{%0,%1,%2,%3}, {%4,%5,%6,%7}, {%8,%9}, {%0,%1,%2,%3};"
        : "+f"(d.x), "+f"(d.y), "+f"(d.z), "+f"(d.w)
        : "r"(a0), "r"(a1), "r"(a2), "r"(a3), "r"(b0), "r"(b1));
}

__device__ __forceinline__ void mma_tf32(float4 &d,
    uint32_t a0, uint32_t a1, uint32_t a2, uint32_t a3, uint32_t b0, uint32_t b1)
{
    asm volatile("mma.sync.aligned.m16n8k8.row.col.f32.tf32.tf32.f32 "
        "{%0,%1,%2,%3}, {%4,%5,%6,%7}, {%8,%9}, {%0,%1,%2,%3};"
        : "+f"(d.x), "+f"(d.y), "+f"(d.z), "+f"(d.w)
        : "r"(a0), "r"(a1), "r"(a2), "r"(a3), "r"(b0), "r"(b1));
}

__device__ __forceinline__ uint32_t f2tf32(float x) {
    uint32_t r; asm("cvt.rna.tf32.f32 %0, %1;" : "=r"(r) : "f"(x)); return r;
}

__device__ __forceinline__ uint4 ldm_x4(uint32_t addr) {
    uint4 r;
    asm volatile("ldmatrix.sync.aligned.m8n8.x4.shared.b16 {%0,%1,%2,%3}, [%4];"
        : "=r"(r.x), "=r"(r.y), "=r"(r.z), "=r"(r.w) : "r"(addr));
    return r;
}

__device__ __forceinline__ void cp16(uint32_t saddr, const void* g) {
    asm volatile("cp.async.cg.shared.global [%0], [%1], 16;" :: "r"(saddr), "l"(g));
}
#define CP_COMMIT() asm volatile("cp.async.commit_group;")

__device__ __forceinline__ uint32_t pack2(__nv_bfloat16 a, __nv_bfloat16 b) {
    __nv_bfloat162 t; t.x = a; t.y = b;
    return *reinterpret_cast<uint32_t*>(&t);
}

__device__ __forceinline__ void split2(float a, float b, uint32_t &hi, uint32_t &lo) {
    __nv_bfloat16 ha = __float2bfloat16_rn(a), hb = __float2bfloat16_rn(b);
    __nv_bfloat16 la = __float2bfloat16_rn(a - __bfloat162float(ha));
    __nv_bfloat16 lb = __float2bfloat16_rn(b - __bfloat162float(hb));
    hi = pack2(ha, hb); lo = pack2(la, lb);
}

// fp32 -> hi/lo bf16 split
__global__ __launch_bounds__(256) void split_kernel(
    const float* __restrict__ in, __nv_bfloat16* __restrict__ hi,
    __nv_bfloat16* __restrict__ lo, int n4)
{
    int i = blockIdx.x * blockDim.x + threadIdx.x;
    if (i >= n4) return;
    float4 v = ((const float4*)in)[i];
    uint32_t h0, l0, h1, l1;
    split2(v.x, v.y, h0, l0);
    split2(v.z, v.w, h1, l1);
    uint32_t* hi32 = (uint32_t*)hi;
    uint32_t* lo32 = (uint32_t*)lo;
    hi32[2*i] = h0; hi32[2*i+1] = h1;
    lo32[2*i] = l0; lo32[2*i+1] = l1;
}

// ---------------------------------------------------------------------------
// bf16x3 GEMM (R12, unchanged): cp.async 3-stage + ldmatrix, 128x128, BK=32,
// 8 warps (2m x 4n), 2 CTAs/SM, single barrier per iter.
// ---------------------------------------------------------------------------
#define GSTAGES 3
#define GSTAGE_BYTES (4 * 8192)
#define GEMM_SMEM (GSTAGES * GSTAGE_BYTES)

__global__ __launch_bounds__(256, 2) void gemm_bf16x3(
    const __nv_bfloat16* __restrict__ Ahi, const __nv_bfloat16* __restrict__ Alo,
    const __nv_bfloat16* __restrict__ Bhi, const __nv_bfloat16* __restrict__ Blo,
    float* __restrict__ C, int M, int N, int K)
{
    extern __shared__ uint8_t gsm8[];
    const uint32_t sbase = (uint32_t)__cvta_generic_to_shared(gsm8);

    const int tid  = threadIdx.x;
    const int lane = tid & 31, wid = tid >> 5;
    const int g = lane >> 2, c = lane & 3;
    const int wm = wid >> 2, wn = wid & 3;
    const int m0 = blockIdx.y * 128, n0 = blockIdx.x * 128;
    const int rsu = K >> 3;

    const int crow = tid >> 1;
    const int cc0  = (tid & 1) * 2;
    const int csw  = (crow >> 1) & 3;
    const uint32_t soff0 = crow * 64 + ((cc0 ^ csw) << 4);
    const uint32_t soff1 = crow * 64 + (((cc0 + 1) ^ csw) << 4);
    const uint4* gAh = (const uint4*)Ahi + (size_t)(m0 + crow) * rsu + cc0;
    const uint4* gAl = (const uint4*)Alo + (size_t)(m0 + crow) * rsu + cc0;
    const uint4* gBh = (const uint4*)Bhi + (size_t)(n0 + crow) * rsu + cc0;
    const uint4* gBl = (const uint4*)Blo + (size_t)(n0 + crow) * rsu + cc0;

    const int sub  = lane >> 3;
    const int arow = wm * 64 + ((sub & 1) << 3) + (lane & 7);
    const int chA  = sub >> 1;
    const uint32_t aoffA0 = arow * 64 + ((chA ^ ((arow >> 1) & 3)) << 4);
    const uint32_t aoffA1 = aoffA0 ^ 32;
    const int brow = wn * 32 + (lane & 7);
    const uint32_t aoffB = brow * 64 + (((lane >> 3) ^ ((brow >> 1) & 3)) << 4);

    float4 d[4][4];
#pragma unroll
    for (int i = 0; i < 4; i++)
#pragma unroll
        for (int j = 0; j < 4; j++) d[i][j] = make_float4(0.f, 0.f, 0.f, 0.f);

    auto issue = [&](int tile) {
        const uint32_t sb = sbase + (tile % GSTAGES) * GSTAGE_BYTES;
        const int kc = tile * 4;
        cp16(sb + soff0,         gAh + kc);     cp16(sb + soff1,         gAh + kc + 1);
        cp16(sb + 8192  + soff0, gAl + kc);     cp16(sb + 8192  + soff1, gAl + kc + 1);
        cp16(sb + 16384 + soff0, gBh + kc);     cp16(sb + 16384 + soff1, gBh + kc + 1);
        cp16(sb + 24576 + soff0, gBl + kc);     cp16(sb + 24576 + soff1, gBl + kc + 1);
    };

    const int nit = K >> 5;
    issue(0); CP_COMMIT();
    issue(1); CP_COMMIT();

    for (int it = 0; it < nit; it++) {
        if (it + 1 < nit) { asm volatile("cp.async.wait_group 1;"); }
        else              { asm volatile("cp.async.wait_group 0;"); }
        __syncthreads();
        if (it + 2 < nit) { issue(it + 2); CP_COMMIT(); }

        const uint32_t sb  = sbase + (it % GSTAGES) * GSTAGE_BYTES;
        const uint32_t bA  = sb + aoffA0;
        const uint32_t bA1 = sb + aoffA1;
        const uint32_t bB  = sb + 16384 + aoffB;

        uint4 bh[4], bl[4];
#pragma unroll
        for (int in_ = 0; in_ < 4; in_++) {
            bh[in_] = ldm_x4(bB + in_ * 512);
            bl[in_] = ldm_x4(bB + 8192 + in_ * 512);
        }
#pragma unroll
        for (int im = 0; im < 4; im++) {
            uint4 ah0 = ldm_x4(bA  + im * 1024);
            uint4 ah1 = ldm_x4(bA1 + im * 1024);
            uint4 al0 = ldm_x4(bA  + 8192 + im * 1024);
            uint4 al1 = ldm_x4(bA1 + 8192 + im * 1024);
#pragma unroll
            for (int in_ = 0; in_ < 4; in_++) {
                mma_bf16(d[im][in_], ah0.x, ah0.y, ah0.z, ah0.w, bh[in_].x, bh[in_].y);
                mma_bf16(d[im][in_], ah0.x, ah0.y, ah0.z, ah0.w, bl[in_].x, bl[in_].y);
                mma_bf16(d[im][in_], al0.x, al0.y, al0.z, al0.w, bh[in_].x, bh[in_].y);
                mma_bf16(d[im][in_], ah1.x, ah1.y, ah1.z, ah1.w, bh[in_].z, bh[in_].w);
                mma_bf16(d[im][in_], ah1.x, ah1.y, ah1.z, ah1.w, bl[in_].z, bl[in_].w);
                mma_bf16(d[im][in_], al1.x, al1.y, al1.z, al1.w, bh[in_].z, bh[in_].w);
            }
        }
    }

#pragma unroll
    for (int im = 0; im < 4; im++)
#pragma unroll
        for (int in_ = 0; in_ < 4; in_++) {
            int row = m0 + wm * 64 + im * 16 + g;
            int col = n0 + wn * 32 + in_ * 8 + 2 * c;
            *(float2*)&C[(size_t)row * N + col]       = make_float2(d[im][in_].x, d[im][in_].y);
            *(float2*)&C[(size_t)(row + 8) * N + col] = make_float2(d[im][in_].z, d[im][in_].w);
        }
}

// ---------------------------------------------------------------------------
// LN (per-head) + rotary, in-place fp32 on qkv; q pre-scaled by 1/8.
// ---------------------------------------------------------------------------
__global__ __launch_bounds__(256) void ln_rope_kernel(
    float* __restrict__ qkv, const float* __restrict__ rope,
    const float* __restrict__ qg, const float* __restrict__ qb,
    const float* __restrict__ kg, const float* __restrict__ kb)
{
    int wid  = (blockIdx.x * blockDim.x + threadIdx.x) >> 5;
    int lane = threadIdx.x & 31;
    int which = wid & 1;
    int rowh  = wid >> 1;
    int h  = rowh & 31;
    int bs = rowh >> 5;
    int s  = bs & (S_ - 1);

    float* p = qkv + (size_t)bs * C3 + h * 192 + which * 64;
    float x0 = p[lane];
    float x1 = p[lane + 32];

    float sum = x0 + x1;
#pragma unroll
    for (int off = 16; off > 0; off >>= 1) sum += __shfl_xor_sync(0xffffffffu, sum, off);
    float mean = sum * (1.0f / 64.0f);
    float d0 = x0 - mean, d1 = x1 - mean;
    float vs = d0 * d0 + d1 * d1;
#pragma unroll
    for (int off = 16; off > 0; off >>= 1) vs += __shfl_xor_sync(0xffffffffu, vs, off);
    float rstd = rsqrtf(vs * (1.0f / 64.0f) + 1e-5f);

    const float* gm = which ? kg : qg;
    const float* bt = which ? kb : qb;
    float y0 = d0 * rstd * gm[lane]      + bt[lane];
    float y1 = d1 * rstd * gm[lane + 32] + bt[lane + 32];

    float pr0 = __shfl_xor_sync(0xffffffffu, y0, 1);
    float pr1 = __shfl_xor_sync(0xffffffffu, y1, 1);
    int j = lane & 1;
    const float* rb = rope + s * 128;

    int i0 = lane >> 1;
    float e0 = j ? pr0 : y0;
    float o0 = j ? y0 : pr0;
    float out0 = rb[i0 * 4 + j * 2 + 0] * e0 + rb[i0 * 4 + j * 2 + 1] * o0;

    int i1 = (lane + 32) >> 1;
    float e1 = j ? pr1 : y1;
    float o1 = j ? y1 : pr1;
    float out1 = rb[i1 * 4 + j * 2 + 0] * e1 + rb[i1 * 4 + j * 2 + 1] * o1;

    if (which == 0) { out0 *= 0.125f; out1 *= 0.125f; }   // fold score scale into q

    p[lane]      = out0;
    p[lane + 32] = out1;
}

// ---------------------------------------------------------------------------
// Flash attention, tf32 single-pass (R3-validated layout). Block = 128 q rows
// of one (b,h), 8 warps; warp w owns rows [w*16, w*16+16) -> warp-local softmax.
// Ks/Vs: [64][68] tf32; Ps: [128][68] tf32 (Q staging, then P round-trip).
// K/V tile loads register-prefetched one tile ahead to hide LDG/L2 latency.
// Epilogue writes split bf16 hi/lo for the bf16x3 out-projection.
// ---------------------------------------------------------------------------
#define AP 68
#define ATT_SMEM ((64 + 64 + 128) * AP * 4)   // 69632 bytes

__global__ __launch_bounds__(256) void attn_tf32(
    const float* __restrict__ qkv,
    __nv_bfloat16* __restrict__ atthi, __nv_bfloat16* __restrict__ attlo)
{
    extern __shared__ uint32_t dsm[];
    uint32_t* Ks = dsm;                 // [64][AP]
    uint32_t* Vs = dsm + 64 * AP;       // [64][AP]
    uint32_t* Ps = dsm + 128 * AP;      // [128][AP]

    const int tid = threadIdx.x, lane = tid & 31, wid = tid >> 5;
    const int g = lane >> 2, c = lane & 3;
    const int q0 = blockIdx.x * 128;
    const int h  = blockIdx.y, b = blockIdx.z;
    const int w16 = wid * 16;

    // ---- stage Q (pre-scaled in ln_rope) into Ps, pull fragments ----
#pragma unroll
    for (int i = 0; i < 8; i++) {
        int lin = tid + i * 256;
        int row = lin >> 4, dc = lin & 15;
        float4 v = *(const float4*)&qkv[(size_t)(b * S_ + q0 + row) * C3 + h * 192 + dc * 4];
        *(uint4*)&Ps[row * AP + dc * 4] =
            make_uint4(f2tf32(v.x), f2tf32(v.y), f2tf32(v.z), f2tf32(v.w));
    }
    __syncthreads();
    uint32_t Qf[8][4];
#pragma unroll
    for (int s = 0; s < 8; s++) {
        Qf[s][0] = Ps[(w16 + g)     * AP + 8 * s + c];
        Qf[s][1] = Ps[(w16 + g + 8) * AP + 8 * s + c];
        Qf[s][2] = Ps[(w16 + g)     * AP + 8 * s + c + 4];
        Qf[s][3] = Ps[(w16 + g + 8) * AP + 8 * s + c + 4];
    }

    float m_lo = -1e30f, m_hi = -1e30f, l_lo = 0.f, l_hi = 0.f;
    float4 acc[8];
#pragma unroll
    for (int nt = 0; nt < 8; nt++) acc[nt] = make_float4(0.f, 0.f, 0.f, 0.f);

    // K/V register prefetch (one tile ahead)
    float4 pk[4], pv[4];
    auto ldtile = [&](int kv0) {
#pragma unroll
        for (int i2 = 0; i2 < 4; i2++) {
            int lin = tid + i2 * 256;
            int row = lin >> 4, dc = lin & 15;
            const float* base = &qkv[(size_t)(b * S_ + kv0 + row) * C3 + h * 192];
            pk[i2] = *(const float4*)(base + 64  + dc * 4);
            pv[i2] = *(const float4*)(base + 128 + dc * 4);
        }
    };
    ldtile(0);

    for (int i = 0; i < 32; i++) {
        __syncthreads();   // prev tile's compute done reading Ks/Vs/Ps (and Qf reads, i=0)
#pragma unroll
        for (int i2 = 0; i2 < 4; i2++) {
            int lin = tid + i2 * 256;
            int row = lin >> 4, dc = lin & 15;
            *(uint4*)&Ks[row * AP + dc * 4] =
                make_uint4(f2tf32(pk[i2].x), f2tf32(pk[i2].y), f2tf32(pk[i2].z), f2tf32(pk[i2].w));
            *(uint4*)&Vs[row * AP + dc * 4] =
                make_uint4(f2tf32(pv[i2].x), f2tf32(pv[i2].y), f2tf32(pv[i2].z), f2tf32(pv[i2].w));
        }
        __syncthreads();
        if (i + 1 < 32) ldtile((i + 1) * 64);   // prefetch next tile (regs free now)

        // ---- S = Q K^T ----
        float4 sf[8];
#pragma unroll
        for (int nt = 0; nt < 8; nt++) sf[nt] = make_float4(0.f, 0.f, 0.f, 0.f);
#pragma unroll
        for (int s = 0; s < 8; s++) {
#pragma unroll
            for (int nt = 0; nt < 8; nt++) {
                uint32_t b0 = Ks[(nt * 8 + g) * AP + 8 * s + c];
                uint32_t b1 = Ks[(nt * 8 + g) * AP + 8 * s + c + 4];
                mma_tf32(sf[nt], Qf[s][0], Qf[s][1], Qf[s][2], Qf[s][3], b0, b1);
            }
        }

        // ---- warp-local online softmax (rows g and g+8) ----
        float tlo = -1e30f, thi = -1e30f;
#pragma unroll
        for (int nt = 0; nt < 8; nt++) {
            tlo = fmaxf(tlo, fmaxf(sf[nt].x, sf[nt].y));
            thi = fmaxf(thi, fmaxf(sf[nt].z, sf[nt].w));
        }
        tlo = fmaxf(tlo, __shfl_xor_sync(0xffffffffu, tlo, 1));
        tlo = fmaxf(tlo, __shfl_xor_sync(0xffffffffu, tlo, 2));
        thi = fmaxf(thi, __shfl_xor_sync(0xffffffffu, thi, 1));
        thi = fmaxf(thi, __shfl_xor_sync(0xffffffffu, thi, 2));

        float mnlo = fmaxf(m_lo, tlo), mnhi = fmaxf(m_hi, thi);
        float corlo = __expf(m_lo - mnlo), corhi = __expf(m_hi - mnhi);
        float slo = 0.f, shi = 0.f;
#pragma unroll
        for (int nt = 0; nt < 8; nt++) {
            sf[nt].x = __expf(sf[nt].x - mnlo);
            sf[nt].y = __expf(sf[nt].y - mnlo);
            sf[nt].z = __expf(sf[nt].z - mnhi);
            sf[nt].w = __expf(sf[nt].w - mnhi);
            slo += sf[nt].x + sf[nt].y;
            shi += sf[nt].z + sf[nt].w;
        }
        slo += __shfl_xor_sync(0xffffffffu, slo, 1);
        slo += __shfl_xor_sync(0xffffffffu, slo, 2);
        shi += __shfl_xor_sync(0xffffffffu, shi, 1);
        shi += __shfl_xor_sync(0xffffffffu, shi, 2);
        l_lo = l_lo * corlo + slo;
        l_hi = l_hi * corhi + shi;
        m_lo = mnlo; m_hi = mnhi;
#pragma unroll
        for (int nt = 0; nt < 8; nt++) {
            acc[nt].x *= corlo; acc[nt].y *= corlo;
            acc[nt].z *= corhi; acc[nt].w *= corhi;
        }

        // store P (tf32) to Ps
#pragma unroll
        for (int nt = 0; nt < 8; nt++) {
            Ps[(w16 + g)     * AP + nt * 8 + 2 * c]     = f2tf32(sf[nt].x);
            Ps[(w16 + g)     * AP + nt * 8 + 2 * c + 1] = f2tf32(sf[nt].y);
            Ps[(w16 + g + 8) * AP + nt * 8 + 2 * c]     = f2tf32(sf[nt].z);
            Ps[(w16 + g + 8) * AP + nt * 8 + 2 * c + 1] = f2tf32(sf[nt].w);
        }
        __syncthreads();

        // ---- O += P V ----
#pragma unroll
        for (int s = 0; s < 8; s++) {
            uint32_t a0 = Ps[(w16 + g)     * AP + 8 * s + c];
            uint32_t a1 = Ps[(w16 + g + 8) * AP + 8 * s + c];
            uint32_t a2 = Ps[(w16 + g)     * AP + 8 * s + c + 4];
            uint32_t a3 = Ps[(w16 + g + 8) * AP + 8 * s + c + 4];
#pragma unroll
            for (int nt = 0; nt < 8; nt++) {
                uint32_t b0 = Vs[(8 * s + c)     * AP + nt * 8 + g];
                uint32_t b1 = Vs[(8 * s + c + 4) * AP + nt * 8 + g];
                mma_tf32(acc[nt], a0, a1, a2, a3, b0, b1);
            }
        }
    }

    // ---- epilogue: normalize + split to bf16 hi/lo for out-proj ----
    float ilo = 1.f / l_lo, ihi = 1.f / l_hi;
    uint32_t* ah32 = (uint32_t*)atthi;
    uint32_t* al32 = (uint32_t*)attlo;
    size_t ob0 = (size_t)(b * S_ + q0 + w16 + g) * 1024 + h * 32;
    size_t ob1 = ob0 + 8 * 1024;
#pragma unroll
    for (int nt = 0; nt < 8; nt++) {
        uint32_t h0, l0, h1, l1;
        split2(acc[nt].x * ilo, acc[nt].y * ilo, h0, l0);
        split2(acc[nt].z * ihi, acc[nt].w * ihi, h1, l1);
        ah32[ob0 + nt * 4 + c] = h0; al32[ob0 + nt * 4 + c] = l0;
        ah32[ob1 + nt * 4 + c] = h1; al32[ob1 + nt * 4 + c] = l1;
    }
}

// ---------------------------------------------------------------------------
extern "C" void kernel_launch(void* const* d_in, const int* in_sizes, int n_in,
                              void* d_out, int out_size)
{
    const float* x     = (const float*)d_in[0];
    const float* rope  = (const float*)d_in[1];
    const float* w_qkv = (const float*)d_in[2];
    const float* w_out = (const float*)d_in[3];
    const float* qg    = (const float*)d_in[4];
    const float* qb    = (const float*)d_in[5];
    const float* kg    = (const float*)d_in[6];
    const float* kb    = (const float*)d_in[7];
    float* out = (float*)d_out;

    cudaFuncSetAttribute(gemm_bf16x3, cudaFuncAttributeMaxDynamicSharedMemorySize, GEMM_SMEM);
    cudaFuncSetAttribute(attn_tf32, cudaFuncAttributeMaxDynamicSharedMemorySize, ATT_SMEM);

    float* qkv; cudaGetSymbolAddress((void**)&qkv, g_qkv);
    __nv_bfloat16 *xhi, *xlo, *wqhi, *wqlo, *wohi, *wolo, *athi, *atlo;
    cudaGetSymbolAddress((void**)&xhi,  g_xhi);  cudaGetSymbolAddress((void**)&xlo,  g_xlo);
    cudaGetSymbolAddress((void**)&wqhi, g_wqhi); cudaGetSymbolAddress((void**)&wqlo, g_wqlo);
    cudaGetSymbolAddress((void**)&wohi, g_wohi); cudaGetSymbolAddress((void**)&wolo, g_wolo);
    cudaGetSymbolAddress((void**)&athi, g_atthi);cudaGetSymbolAddress((void**)&atlo, g_attlo);

    // 0) split inputs/weights
    split_kernel<<<(BS * C_ / 4) / 256, 256>>>(x, xhi, xlo, BS * C_ / 4);
    split_kernel<<<(C3 * C_ / 4) / 256, 256>>>(w_qkv, wqhi, wqlo, C3 * C_ / 4);
    split_kernel<<<(C_ * C_ / 4) / 256, 256>>>(w_out, wohi, wolo, C_ * C_ / 4);

    // 1) QKV projection (bf16x3 -> fp32 qkv)
    gemm_bf16x3<<<dim3(C3 / 128, BS / 128), 256, GEMM_SMEM>>>(
        xhi, xlo, wqhi, wqlo, qkv, BS, C3, C_);

    // 2) LN + rotary, in place (q pre-scaled by 1/8)
    ln_rope_kernel<<<(BS * H_ * 2) / 8, 256>>>(qkv, rope, qg, qb, kg, kb);

    // 3) flash attention (tf32) -> split bf16 att
    attn_tf32<<<dim3(S_ / 128, H_, B_), 256, ATT_SMEM>>>(qkv, athi, atlo);

    // 4) output projection (bf16x3)
    gemm_bf16x3<<<dim3(C_ / 128, BS / 128), 256, GEMM_SMEM>>>(
        athi, atlo, wohi, wolo, out, BS, C_, C_);
}

// round 14
// speedup vs baseline: 1.2970x; 1.0940x over previous
#include <cuda_runtime.h>
#include <cuda_bf16.h>
#include <cstdint>
#include <math.h>

#define B_ 2
#define S_ 2048
#define C_ 2048
#define H_ 32
#define C3 6144
#define BS (B_*S_)

// Scratch (allocation-free device globals)
__device__ float g_qkv[BS * C3];
__device__ __nv_bfloat16 g_xhi[BS * C_],  g_xlo[BS * C_];
__device__ __nv_bfloat16 g_wqhi[C3 * C_], g_wqlo[C3 * C_];
__device__ __nv_bfloat16 g_wohi[C_ * C_], g_wolo[C_ * C_];
__device__ __nv_bfloat16 g_atthi[BS * C_], g_attlo[BS * C_];
__device__ uint32_t g_qtf[(size_t)B_ * H_ * S_ * 64];   // tf32 q, [b,h,s,d]
__device__ uint32_t g_ktf[(size_t)B_ * H_ * S_ * 64];   // tf32 k, [b,h,s,d]
__device__ uint32_t g_vtf[(size_t)B_ * H_ * 64 * S_];   // tf32 v^T, [b,h,d,s]

__device__ __forceinline__ void mma_bf16(float4 &d,
    uint32_t a0, uint32_t a1, uint32_t a2, uint32_t a3, uint32_t b0, uint32_t b1)
{
    asm volatile("mma.sync.aligned.m16n8k16.row.col.f32.bf16.bf16.f32 "
        "{%0,%1,%2,%3}, {%4,%5,%6,%7}, {%8,%9}, {%0,%1,%2,%3};"
        : "+f"(d.x), "+f"(d.y), "+f"(d.z), "+f"(d.w)
        : "r"(a0), "r"(a1), "r"(a2), "r"(a3), "r"(b0), "r"(b1));
}

__device__ __forceinline__ void mma_tf32(float4 &d,
    uint32_t a0, uint32_t a1, uint32_t a2, uint32_t a3, uint32_t b0, uint32_t b1)
{
    asm volatile("mma.sync.aligned.m16n8k8.row.col.f32.tf32.tf32.f32 "
        "{%0,%1,%2,%3}, {%4,%5,%6,%7}, {%8,%9}, {%0,%1,%2,%3};"
        : "+f"(d.x), "+f"(d.y), "+f"(d.z), "+f"(d.w)
        : "r"(a0), "r"(a1), "r"(a2), "r"(a3), "r"(b0), "r"(b1));
}

__device__ __forceinline__ uint32_t f2tf32(float x) {
    uint32_t r; asm("cvt.rna.tf32.f32 %0, %1;" : "=r"(r) : "f"(x)); return r;
}

__device__ __forceinline__ uint4 ldm_x4(uint32_t addr) {
    uint4 r;
    asm volatile("ldmatrix.sync.aligned.m8n8.x4.shared.b16 {%0,%1,%2,%3}, [%4];"
        : "=r"(r.x), "=r"(r.y), "=r"(r.z), "=r"(r.w) : "r"(addr));
    return r;
}

__device__ __forceinline__ void cp16(uint32_t saddr, const void* g) {
    asm volatile("cp.async.cg.shared.global [%0], [%1], 16;" :: "r"(saddr), "l"(g));
}
#define CP_COMMIT() asm volatile("cp.async.commit_group;")

__device__ __forceinline__ uint32_t pack2(__nv_bfloat16 a, __nv_bfloat16 b) {
    __nv_bfloat162 t; t.x = a; t.y = b;
    return *reinterpret_cast<uint32_t*>(&t);
}

__device__ __forceinline__ void split2(float a, float b, uint32_t &hi, uint32_t &lo) {
    __nv_bfloat16 ha = __float2bfloat16_rn(a), hb = __float2bfloat16_rn(b);
    __nv_bfloat16 la = __float2bfloat16_rn(a - __bfloat162float(ha));
    __nv_bfloat16 lb = __float2bfloat16_rn(b - __bfloat162float(hb));
    hi = pack2(ha, hb); lo = pack2(la, lb);
}

// fp32 -> hi/lo bf16 split
__global__ __launch_bounds__(256) void split_kernel(
    const float* __restrict__ in, __nv_bfloat16* __restrict__ hi,
    __nv_bfloat16* __restrict__ lo, int n4)
{
    int i = blockIdx.x * blockDim.x + threadIdx.x;
    if (i >= n4) return;
    float4 v = ((const float4*)in)[i];
    uint32_t h0, l0, h1, l1;
    split2(v.x, v.y, h0, l0);
    split2(v.z, v.w, h1, l1);
    uint32_t* hi32 = (uint32_t*)hi;
    uint32_t* lo32 = (uint32_t*)lo;
    hi32[2*i] = h0; hi32[2*i+1] = h1;
    lo32[2*i] = l0; lo32[2*i+1] = l1;
}

// ---------------------------------------------------------------------------
// bf16x3 GEMM (R12, unchanged)
// ---------------------------------------------------------------------------
#define GSTAGES 3
#define GSTAGE_BYTES (4 * 8192)
#define GEMM_SMEM (GSTAGES * GSTAGE_BYTES)

__global__ __launch_bounds__(256, 2) void gemm_bf16x3(
    const __nv_bfloat16* __restrict__ Ahi, const __nv_bfloat16* __restrict__ Alo,
    const __nv_bfloat16* __restrict__ Bhi, const __nv_bfloat16* __restrict__ Blo,
    float* __restrict__ C, int M, int N, int K)
{
    extern __shared__ uint8_t gsm8[];
    const uint32_t sbase = (uint32_t)__cvta_generic_to_shared(gsm8);

    const int tid  = threadIdx.x;
    const int lane = tid & 31, wid = tid >> 5;
    const int g = lane >> 2, c = lane & 3;
    const int wm = wid >> 2, wn = wid & 3;
    const int m0 = blockIdx.y * 128, n0 = blockIdx.x * 128;
    const int rsu = K >> 3;

    const int crow = tid >> 1;
    const int cc0  = (tid & 1) * 2;
    const int csw  = (crow >> 1) & 3;
    const uint32_t soff0 = crow * 64 + ((cc0 ^ csw) << 4);
    const uint32_t soff1 = crow * 64 + (((cc0 + 1) ^ csw) << 4);
    const uint4* gAh = (const uint4*)Ahi + (size_t)(m0 + crow) * rsu + cc0;
    const uint4* gAl = (const uint4*)Alo + (size_t)(m0 + crow) * rsu + cc0;
    const uint4* gBh = (const uint4*)Bhi + (size_t)(n0 + crow) * rsu + cc0;
    const uint4* gBl = (const uint4*)Blo + (size_t)(n0 + crow) * rsu + cc0;

    const int sub  = lane >> 3;
    const int arow = wm * 64 + ((sub & 1) << 3) + (lane & 7);
    const int chA  = sub >> 1;
    const uint32_t aoffA0 = arow * 64 + ((chA ^ ((arow >> 1) & 3)) << 4);
    const uint32_t aoffA1 = aoffA0 ^ 32;
    const int brow = wn * 32 + (lane & 7);
    const uint32_t aoffB = brow * 64 + (((lane >> 3) ^ ((brow >> 1) & 3)) << 4);

    float4 d[4][4];
#pragma unroll
    for (int i = 0; i < 4; i++)
#pragma unroll
        for (int j = 0; j < 4; j++) d[i][j] = make_float4(0.f, 0.f, 0.f, 0.f);

    auto issue = [&](int tile) {
        const uint32_t sb = sbase + (tile % GSTAGES) * GSTAGE_BYTES;
        const int kc = tile * 4;
        cp16(sb + soff0,         gAh + kc);     cp16(sb + soff1,         gAh + kc + 1);
        cp16(sb + 8192  + soff0, gAl + kc);     cp16(sb + 8192  + soff1, gAl + kc + 1);
        cp16(sb + 16384 + soff0, gBh + kc);     cp16(sb + 16384 + soff1, gBh + kc + 1);
        cp16(sb + 24576 + soff0, gBl + kc);     cp16(sb + 24576 + soff1, gBl + kc + 1);
    };

    const int nit = K >> 5;
    issue(0); CP_COMMIT();
    issue(1); CP_COMMIT();

    for (int it = 0; it < nit; it++) {
        if (it + 1 < nit) { asm volatile("cp.async.wait_group 1;"); }
        else              { asm volatile("cp.async.wait_group 0;"); }
        __syncthreads();
        if (it + 2 < nit) { issue(it + 2); CP_COMMIT(); }

        const uint32_t sb  = sbase + (it % GSTAGES) * GSTAGE_BYTES;
        const uint32_t bA  = sb + aoffA0;
        const uint32_t bA1 = sb + aoffA1;
        const uint32_t bB  = sb + 16384 + aoffB;

        uint4 bh[4], bl[4];
#pragma unroll
        for (int in_ = 0; in_ < 4; in_++) {
            bh[in_] = ldm_x4(bB + in_ * 512);
            bl[in_] = ldm_x4(bB + 8192 + in_ * 512);
        }
#pragma unroll
        for (int im = 0; im < 4; im++) {
            uint4 ah0 = ldm_x4(bA  + im * 1024);
            uint4 ah1 = ldm_x4(bA1 + im * 1024);
            uint4 al0 = ldm_x4(bA  + 8192 + im * 1024);
            uint4 al1 = ldm_x4(bA1 + 8192 + im * 1024);
#pragma unroll
            for (int in_ = 0; in_ < 4; in_++) {
                mma_bf16(d[im][in_], ah0.x, ah0.y, ah0.z, ah0.w, bh[in_].x, bh[in_].y);
                mma_bf16(d[im][in_], ah0.x, ah0.y, ah0.z, ah0.w, bl[in_].x, bl[in_].y);
                mma_bf16(d[im][in_], al0.x, al0.y, al0.z, al0.w, bh[in_].x, bh[in_].y);
                mma_bf16(d[im][in_], ah1.x, ah1.y, ah1.z, ah1.w, bh[in_].z, bh[in_].w);
                mma_bf16(d[im][in_], ah1.x, ah1.y, ah1.z, ah1.w, bl[in_].z, bl[in_].w);
                mma_bf16(d[im][in_], al1.x, al1.y, al1.z, al1.w, bh[in_].z, bh[in_].w);
            }
        }
    }

#pragma unroll
    for (int im = 0; im < 4; im++)
#pragma unroll
        for (int in_ = 0; in_ < 4; in_++) {
            int row = m0 + wm * 64 + im * 16 + g;
            int col = n0 + wn * 32 + in_ * 8 + 2 * c;
            *(float2*)&C[(size_t)row * N + col]       = make_float2(d[im][in_].x, d[im][in_].y);
            *(float2*)&C[(size_t)(row + 8) * N + col] = make_float2(d[im][in_].z, d[im][in_].w);
        }
}

// ---------------------------------------------------------------------------
// LN (per-head) + rotary; q pre-scaled by 1/8; writes tf32 q/k to [b,h,s,d].
// ---------------------------------------------------------------------------
__global__ __launch_bounds__(256) void ln_rope_kernel(
    const float* __restrict__ qkv, const float* __restrict__ rope,
    const float* __restrict__ qg, const float* __restrict__ qb,
    const float* __restrict__ kg, const float* __restrict__ kb,
    uint32_t* __restrict__ qtf, uint32_t* __restrict__ ktf)
{
    int wid  = (blockIdx.x * blockDim.x + threadIdx.x) >> 5;
    int lane = threadIdx.x & 31;
    int which = wid & 1;
    int rowh  = wid >> 1;
    int h  = rowh & 31;
    int bs = rowh >> 5;
    int s  = bs & (S_ - 1);
    int b  = bs >> 11;

    const float* p = qkv + (size_t)bs * C3 + h * 192 + which * 64;
    float x0 = p[lane];
    float x1 = p[lane + 32];

    float sum = x0 + x1;
#pragma unroll
    for (int off = 16; off > 0; off >>= 1) sum += __shfl_xor_sync(0xffffffffu, sum, off);
    float mean = sum * (1.0f / 64.0f);
    float d0 = x0 - mean, d1 = x1 - mean;
    float vs = d0 * d0 + d1 * d1;
#pragma unroll
    for (int off = 16; off > 0; off >>= 1) vs += __shfl_xor_sync(0xffffffffu, vs, off);
    float rstd = rsqrtf(vs * (1.0f / 64.0f) + 1e-5f);

    const float* gm = which ? kg : qg;
    const float* bt = which ? kb : qb;
    float y0 = d0 * rstd * gm[lane]      + bt[lane];
    float y1 = d1 * rstd * gm[lane + 32] + bt[lane + 32];

    float pr0 = __shfl_xor_sync(0xffffffffu, y0, 1);
    float pr1 = __shfl_xor_sync(0xffffffffu, y1, 1);
    int j = lane & 1;
    const float* rb = rope + s * 128;

    int i0 = lane >> 1;
    float e0 = j ? pr0 : y0;
    float o0 = j ? y0 : pr0;
    float out0 = rb[i0 * 4 + j * 2 + 0] * e0 + rb[i0 * 4 + j * 2 + 1] * o0;

    int i1 = (lane + 32) >> 1;
    float e1 = j ? pr1 : y1;
    float o1 = j ? y1 : pr1;
    float out1 = rb[i1 * 4 + j * 2 + 0] * e1 + rb[i1 * 4 + j * 2 + 1] * o1;

    if (which == 0) { out0 *= 0.125f; out1 *= 0.125f; }   // fold score scale into q

    uint32_t* dst = which ? ktf : qtf;
    size_t o = ((size_t)(b * H_ + h) * S_ + s) * 64;
    dst[o + lane]      = f2tf32(out0);
    dst[o + lane + 32] = f2tf32(out1);
}

// ---------------------------------------------------------------------------
// V -> tf32 transposed [b,h,d,s]
// ---------------------------------------------------------------------------
__global__ __launch_bounds__(256) void vt_tf32_kernel(
    const float* __restrict__ qkv, uint32_t* __restrict__ vtf)
{
    __shared__ uint32_t sv[64 * 76];

    const int tid = threadIdx.x;
    const int s0 = blockIdx.x * 64, h = blockIdx.y, b = blockIdx.z;
    const int tok = tid >> 2, q = tid & 3;

#pragma unroll
    for (int it = 0; it < 4; it++) {
        int dd = q * 16 + it * 4;
        float4 v = *(const float4*)&qkv[(size_t)(b * S_ + s0 + tok) * C3 + h * 192 + 128 + dd];
        sv[(dd + 0) * 76 + tok] = f2tf32(v.x);
        sv[(dd + 1) * 76 + tok] = f2tf32(v.y);
        sv[(dd + 2) * 76 + tok] = f2tf32(v.z);
        sv[(dd + 3) * 76 + tok] = f2tf32(v.w);
    }
    __syncthreads();

    const int dr = tid >> 2, cq = tid & 3;
    size_t gbase = ((size_t)(b * H_ + h) * 64 + dr) * S_ + s0 + cq * 16;
#pragma unroll
    for (int u = 0; u < 4; u++)
        *(uint4*)&vtf[gbase + u * 4] = *(const uint4*)&sv[dr * 76 + cq * 16 + u * 4];
}

// ---------------------------------------------------------------------------
// Flash attention tf32 v2: cp.async double-buffered K/Vt tiles (pre-converted
// tf32 in gmem), Vt d-major in smem (conflict-free PV B loads), 2 CTAs/SM.
// Block = 128 q rows of one (b,h), 8 warps, warp-local softmax, P via smem.
// Smem (words): [K0|V0|K1|V1|Ps] = 4*4352 + 128*68 = 26112 -> 104448 B.
// ---------------------------------------------------------------------------
#define AP 68
#define KVW (64 * AP)                       // 4352 words per K or V stage
#define ATT_SMEM ((4 * KVW + 128 * AP) * 4) // 104448 bytes

__global__ __launch_bounds__(256, 2) void attn_tf32(
    const uint32_t* __restrict__ qtf, const uint32_t* __restrict__ ktf,
    const uint32_t* __restrict__ vtf,
    __nv_bfloat16* __restrict__ atthi, __nv_bfloat16* __restrict__ attlo)
{
    extern __shared__ uint32_t dsm[];
    uint32_t* Ps = dsm + 4 * KVW;
    const uint32_t sabase = (uint32_t)__cvta_generic_to_shared(dsm);

    const int tid = threadIdx.x, lane = tid & 31, wid = tid >> 5;
    const int g = lane >> 2, c = lane & 3;
    const int q0 = blockIdx.x * 128;
    const int h  = blockIdx.y, b = blockIdx.z;
    const int w16 = wid * 16;
    const size_t bh = (size_t)(b * H_ + h);

    const uint4* kt4 = (const uint4*)ktf;
    const uint4* vt4 = (const uint4*)vtf;
    const int trow = tid >> 2;            // unused helper removed
    (void)trow;

    auto issueA = [&](int i) {
        const uint32_t sb = sabase + (i & 1) * (2 * KVW * 4);
        const int kv0 = i * 64;
#pragma unroll
        for (int j2 = 0; j2 < 4; j2++) {
            int lin = tid + j2 * 256;         // 0..1023
            int row = lin >> 4, ch = lin & 15;
            uint32_t so = (row * AP + ch * 4) * 4;
            cp16(sb + so,           kt4 + (bh * S_ + kv0 + row) * 16 + ch);
            cp16(sb + KVW * 4 + so, vt4 + (bh * 64 + row) * (S_ >> 2) + (kv0 >> 2) + ch);
        }
    };

    // kick off tile 0 load, then stage Q into Ps (overlapped)
    issueA(0); CP_COMMIT();

#pragma unroll
    for (int i = 0; i < 8; i++) {
        int lin = tid + i * 256;
        int row = lin >> 4, dc = lin & 15;
        uint4 v = *(const uint4*)&qtf[(bh * S_ + q0 + row) * 64 + dc * 4];
        *(uint4*)&Ps[row * AP + dc * 4] = v;
    }
    __syncthreads();
    uint32_t Qf[8][4];
#pragma unroll
    for (int s = 0; s < 8; s++) {
        Qf[s][0] = Ps[(w16 + g)     * AP + 8 * s + c];
        Qf[s][1] = Ps[(w16 + g + 8) * AP + 8 * s + c];
        Qf[s][2] = Ps[(w16 + g)     * AP + 8 * s + c + 4];
        Qf[s][3] = Ps[(w16 + g + 8) * AP + 8 * s + c + 4];
    }

    float m_lo = -1e30f, m_hi = -1e30f, l_lo = 0.f, l_hi = 0.f;
    float4 acc[8];
#pragma unroll
    for (int nt = 0; nt < 8; nt++) acc[nt] = make_float4(0.f, 0.f, 0.f, 0.f);

    for (int i = 0; i < 32; i++) {
        asm volatile("cp.async.wait_group 0;");
        __syncthreads();   // tile data visible; prev PV/P reads done; Qf pulls done (i=0)
        if (i + 1 < 32) { issueA(i + 1); CP_COMMIT(); }

        const uint32_t* Ks = dsm + (i & 1) * (2 * KVW);
        const uint32_t* Vs = Ks + KVW;

        // ---- S = Q K^T ----
        float4 sf[8];
#pragma unroll
        for (int nt = 0; nt < 8; nt++) sf[nt] = make_float4(0.f, 0.f, 0.f, 0.f);
#pragma unroll
        for (int s = 0; s < 8; s++) {
#pragma unroll
            for (int nt = 0; nt < 8; nt++) {
                uint32_t b0 = Ks[(nt * 8 + g) * AP + 8 * s + c];
                uint32_t b1 = Ks[(nt * 8 + g) * AP + 8 * s + c + 4];
                mma_tf32(sf[nt], Qf[s][0], Qf[s][1], Qf[s][2], Qf[s][3], b0, b1);
            }
        }

        // ---- warp-local online softmax (rows g and g+8) ----
        float tlo = -1e30f, thi = -1e30f;
#pragma unroll
        for (int nt = 0; nt < 8; nt++) {
            tlo = fmaxf(tlo, fmaxf(sf[nt].x, sf[nt].y));
            thi = fmaxf(thi, fmaxf(sf[nt].z, sf[nt].w));
        }
        tlo = fmaxf(tlo, __shfl_xor_sync(0xffffffffu, tlo, 1));
        tlo = fmaxf(tlo, __shfl_xor_sync(0xffffffffu, tlo, 2));
        thi = fmaxf(thi, __shfl_xor_sync(0xffffffffu, thi, 1));
        thi = fmaxf(thi, __shfl_xor_sync(0xffffffffu, thi, 2));

        float mnlo = fmaxf(m_lo, tlo), mnhi = fmaxf(m_hi, thi);
        float corlo = __expf(m_lo - mnlo), corhi = __expf(m_hi - mnhi);
        float slo = 0.f, shi = 0.f;
#pragma unroll
        for (int nt = 0; nt < 8; nt++) {
            sf[nt].x = __expf(sf[nt].x - mnlo);
            sf[nt].y = __expf(sf[nt].y - mnlo);
            sf[nt].z = __expf(sf[nt].z - mnhi);
            sf[nt].w = __expf(sf[nt].w - mnhi);
            slo += sf[nt].x + sf[nt].y;
            shi += sf[nt].z + sf[nt].w;
        }
        slo += __shfl_xor_sync(0xffffffffu, slo, 1);
        slo += __shfl_xor_sync(0xffffffffu, slo, 2);
        shi += __shfl_xor_sync(0xffffffffu, shi, 1);
        shi += __shfl_xor_sync(0xffffffffu, shi, 2);
        l_lo = l_lo * corlo + slo;
        l_hi = l_hi * corhi + shi;
        m_lo = mnlo; m_hi = mnhi;
#pragma unroll
        for (int nt = 0; nt < 8; nt++) {
            acc[nt].x *= corlo; acc[nt].y *= corlo;
            acc[nt].z *= corhi; acc[nt].w *= corhi;
        }

        // store P (tf32) to Ps
#pragma unroll
        for (int nt = 0; nt < 8; nt++) {
            Ps[(w16 + g)     * AP + nt * 8 + 2 * c]     = f2tf32(sf[nt].x);
            Ps[(w16 + g)     * AP + nt * 8 + 2 * c + 1] = f2tf32(sf[nt].y);
            Ps[(w16 + g + 8) * AP + nt * 8 + 2 * c]     = f2tf32(sf[nt].z);
            Ps[(w16 + g + 8) * AP + nt * 8 + 2 * c + 1] = f2tf32(sf[nt].w);
        }
        __syncthreads();

        // ---- O += P V  (Vt d-major: B loads conflict-free) ----
#pragma unroll
        for (int s = 0; s < 8; s++) {
            uint32_t a0 = Ps[(w16 + g)     * AP + 8 * s + c];
            uint32_t a1 = Ps[(w16 + g + 8) * AP + 8 * s + c];
            uint32_t a2 = Ps[(w16 + g)     * AP + 8 * s + c + 4];
            uint32_t a3 = Ps[(w16 + g + 8) * AP + 8 * s + c + 4];
#pragma unroll
            for (int nt = 0; nt < 8; nt++) {
                uint32_t b0 = Vs[(nt * 8 + g) * AP + 8 * s + c];
                uint32_t b1 = Vs[(nt * 8 + g) * AP + 8 * s + c + 4];
                mma_tf32(acc[nt], a0, a1, a2, a3, b0, b1);
            }
        }
    }

    // ---- epilogue: normalize + split to bf16 hi/lo for out-proj ----
    float ilo = 1.f / l_lo, ihi = 1.f / l_hi;
    uint32_t* ah32 = (uint32_t*)atthi;
    uint32_t* al32 = (uint32_t*)attlo;
    size_t ob0 = (size_t)(b * S_ + q0 + w16 + g) * 1024 + h * 32;
    size_t ob1 = ob0 + 8 * 1024;
#pragma unroll
    for (int nt = 0; nt < 8; nt++) {
        uint32_t h0, l0, h1, l1;
        split2(acc[nt].x * ilo, acc[nt].y * ilo, h0, l0);
        split2(acc[nt].z * ihi, acc[nt].w * ihi, h1, l1);
        ah32[ob0 + nt * 4 + c] = h0; al32[ob0 + nt * 4 + c] = l0;
        ah32[ob1 + nt * 4 + c] = h1; al32[ob1 + nt * 4 + c] = l1;
    }
}

// ---------------------------------------------------------------------------
extern "C" void kernel_launch(void* const* d_in, const int* in_sizes, int n_in,
                              void* d_out, int out_size)
{
    const float* x     = (const float*)d_in[0];
    const float* rope  = (const float*)d_in[1];
    const float* w_qkv = (const float*)d_in[2];
    const float* w_out = (const float*)d_in[3];
    const float* qg    = (const float*)d_in[4];
    const float* qb    = (const float*)d_in[5];
    const float* kg    = (const float*)d_in[6];
    const float* kb    = (const float*)d_in[7];
    float* out = (float*)d_out;

    cudaFuncSetAttribute(gemm_bf16x3, cudaFuncAttributeMaxDynamicSharedMemorySize, GEMM_SMEM);
    cudaFuncSetAttribute(attn_tf32, cudaFuncAttributeMaxDynamicSharedMemorySize, ATT_SMEM);

    float* qkv; cudaGetSymbolAddress((void**)&qkv, g_qkv);
    __nv_bfloat16 *xhi, *xlo, *wqhi, *wqlo, *wohi, *wolo, *athi, *atlo;
    uint32_t *qtf, *ktf, *vtf;
    cudaGetSymbolAddress((void**)&xhi,  g_xhi);  cudaGetSymbolAddress((void**)&xlo,  g_xlo);
    cudaGetSymbolAddress((void**)&wqhi, g_wqhi); cudaGetSymbolAddress((void**)&wqlo, g_wqlo);
    cudaGetSymbolAddress((void**)&wohi, g_wohi); cudaGetSymbolAddress((void**)&wolo, g_wolo);
    cudaGetSymbolAddress((void**)&athi, g_atthi);cudaGetSymbolAddress((void**)&atlo, g_attlo);
    cudaGetSymbolAddress((void**)&qtf,  g_qtf);  cudaGetSymbolAddress((void**)&ktf,  g_ktf);
    cudaGetSymbolAddress((void**)&vtf,  g_vtf);

    // 0) split inputs/weights
    split_kernel<<<(BS * C_ / 4) / 256, 256>>>(x, xhi, xlo, BS * C_ / 4);
    split_kernel<<<(C3 * C_ / 4) / 256, 256>>>(w_qkv, wqhi, wqlo, C3 * C_ / 4);
    split_kernel<<<(C_ * C_ / 4) / 256, 256>>>(w_out, wohi, wolo, C_ * C_ / 4);

    // 1) QKV projection (bf16x3 -> fp32 qkv)
    gemm_bf16x3<<<dim3(C3 / 128, BS / 128), 256, GEMM_SMEM>>>(
        xhi, xlo, wqhi, wqlo, qkv, BS, C3, C_);

    // 2) LN + rotary -> tf32 q/k [b,h,s,d] (q pre-scaled by 1/8)
    ln_rope_kernel<<<(BS * H_ * 2) / 8, 256>>>(qkv, rope, qg, qb, kg, kb, qtf, ktf);

    // 3) V -> tf32 transposed [b,h,d,s]
    vt_tf32_kernel<<<dim3(S_ / 64, H_, B_), 256>>>(qkv, vtf);

    // 4) flash attention (tf32) -> split bf16 att
    attn_tf32<<<dim3(S_ / 128, H_, B_), 256, ATT_SMEM>>>(qtf, ktf, vtf, athi, atlo);

    // 5) output projection (bf16x3)
    gemm_bf16x3<<<dim3(C_ / 128, BS / 128), 256, GEMM_SMEM>>>(
        athi, atlo, wohi, wolo, out, BS, C_, C_);
}